// round 8
// baseline (speedup 1.0000x reference)
#include <cuda_runtime.h>
#include <cuda_bf16.h>
#include <cstdint>

// ---------------------------------------------------------------------------
// Problem constants
// ---------------------------------------------------------------------------
#define BATCH   64
#define SEQ     2048
#define CIN     32
#define WIN     20
#define DIN     (WIN * CIN)      // 640
#define DP      (DIN / 2)        // 320
#define HID     128
#define G4      (4 * HID)        // 512
#define L_OUT   (SEQ - WIN)      // 2028
#define XT      2032             // padded time stride for g_xpre
#define LBL     48

// ---------------------------------------------------------------------------
// Scratch (static __device__ arrays; no cudaMalloc allowed)
// ---------------------------------------------------------------------------
__device__ float g_wc[DIN * G4];                       // combined proj->ih0 weight [d][g]
__device__ float g_bias0[G4];
__device__ float g_xpre[(size_t)BATCH * G4 * XT];      // preactivations, [b][g][t] (t-major)
__device__ float g_hseq[(size_t)BATCH * L_OUT * HID];  // per-step hidden outputs [b][t][h]

// ---------------------------------------------------------------------------
// Packed fp32x2 helpers
// ---------------------------------------------------------------------------
__device__ __forceinline__ unsigned long long pk2(float x, float y) {
    unsigned long long r;
    asm("mov.b64 %0, {%1, %2};" : "=l"(r) : "f"(x), "f"(y));
    return r;
}
__device__ __forceinline__ float2 unpk2(unsigned long long v) {
    float2 r;
    asm("mov.b64 {%0, %1}, %2;" : "=f"(r.x), "=f"(r.y) : "l"(v));
    return r;
}
__device__ __forceinline__ void fma2(unsigned long long& d, unsigned long long a,
                                     unsigned long long b) {
    asm("fma.rn.f32x2 %0, %1, %2, %3;" : "=l"(d) : "l"(a), "l"(b), "l"(d));
}

// ---------------------------------------------------------------------------
// Cluster / mbarrier helpers
// ---------------------------------------------------------------------------
__device__ __forceinline__ unsigned smem_u32(const void* p) {
    return (unsigned)__cvta_generic_to_shared(p);
}
__device__ __forceinline__ unsigned mapa_rank(unsigned addr, unsigned rank) {
    unsigned r;
    asm("mapa.shared::cluster.u32 %0, %1, %2;" : "=r"(r) : "r"(addr), "r"(rank));
    return r;
}
__device__ __forceinline__ void mbar_init(unsigned addr, unsigned cnt) {
    asm volatile("mbarrier.init.shared.b64 [%0], %1;" :: "r"(addr), "r"(cnt) : "memory");
}
__device__ __forceinline__ void mbar_expect_tx(unsigned addr, unsigned bytes) {
    asm volatile("mbarrier.arrive.expect_tx.shared.b64 _, [%0], %1;"
                 :: "r"(addr), "r"(bytes) : "memory");
}
__device__ __forceinline__ void fence_proxy_async_cta() {
    asm volatile("fence.proxy.async.shared::cta;" ::: "memory");
}
__device__ __forceinline__ void bulk_copy_to_peer(unsigned dst_cluster, unsigned src_cta,
                                                  unsigned bytes, unsigned peer_mbar) {
    asm volatile(
        "cp.async.bulk.shared::cluster.shared::cta.mbarrier::complete_tx::bytes "
        "[%0], [%1], %2, [%3];"
        :: "r"(dst_cluster), "r"(src_cta), "r"(bytes), "r"(peer_mbar) : "memory");
}
__device__ __forceinline__ void mbar_wait_cluster(unsigned addr, unsigned parity) {
    asm volatile(
        "{\n\t"
        ".reg .pred P1;\n\t"
        "WAIT_%=:\n\t"
        "mbarrier.try_wait.parity.acquire.cluster.shared::cta.b64 P1, [%0], %1, 0x989680;\n\t"
        "@P1 bra.uni DONE_%=;\n\t"
        "bra.uni WAIT_%=;\n\t"
        "DONE_%=:\n\t"
        "}"
        :: "r"(addr), "r"(parity) : "memory");
}
__device__ __forceinline__ void cluster_barrier() {
    asm volatile("barrier.cluster.arrive.aligned;" ::: "memory");
    asm volatile("barrier.cluster.wait.aligned;" ::: "memory");
}

// ---------------------------------------------------------------------------
// Fast activations (fp32, ~1e-6 rel error)
// ---------------------------------------------------------------------------
__device__ __forceinline__ float fast_sigmoid(float x) {
    return 1.f / (1.f + __expf(-x));
}
__device__ __forceinline__ float fast_tanh(float x) {
    float ax = fabsf(x);
    float e  = __expf(-2.f * ax);
    float r  = __fdividef(1.f - e, 1.f + e);
    return copysignf(r, x);
}

// ---------------------------------------------------------------------------
// Kernel 1: fold projection into layer-0 input weight.
// ---------------------------------------------------------------------------
__global__ void combine_kernel(const float* __restrict__ proj_w,
                               const float* __restrict__ w_ih0) {
    __shared__ float sPW[32][32];
    __shared__ float sWI[32][33];
    int tx = threadIdx.x, ty = threadIdx.y;
    int d0 = blockIdx.x * 32, g0 = blockIdx.y * 32;
    float acc = 0.f;
    for (int p0 = 0; p0 < DP; p0 += 32) {
        sPW[ty][tx] = proj_w[(size_t)(p0 + ty) * DIN + d0 + tx];
        sWI[ty][tx] = w_ih0[(size_t)(g0 + ty) * DP + p0 + tx];
        __syncthreads();
#pragma unroll
        for (int p = 0; p < 32; p++) acc += sPW[p][tx] * sWI[ty][p];
        __syncthreads();
    }
    g_wc[(size_t)(d0 + tx) * G4 + g0 + ty] = acc;
}

__global__ void bias0_kernel(const float* __restrict__ proj_b,
                             const float* __restrict__ w_ih0,
                             const float* __restrict__ b_ih0,
                             const float* __restrict__ b_hh0) {
    int gidx = threadIdx.x;
    float acc = b_ih0[gidx] + b_hh0[gidx];
    const float* wr = w_ih0 + (size_t)gidx * DP;
    for (int p = 0; p < DP; p++) acc += proj_b[p] * wr[p];
    g_bias0[gidx] = acc;
}

// ---------------------------------------------------------------------------
// Kernel 2: layer-0 preactivations (implicit sliding-window GEMM).
// Output transposed: g_xpre[b][g][t].
// ---------------------------------------------------------------------------
__global__ void __launch_bounds__(256)
xpre0_kernel(const float* __restrict__ in) {
    __shared__ __align__(16) float sIn[128 * 32 + DIN];
    __shared__ __align__(16) float sB[32][64];

    int tid = threadIdx.x;
    int tx = tid & 15, ty = tid >> 4;
    int t0 = blockIdx.x * 128;
    int n0 = blockIdx.y * 64;
    int b  = blockIdx.z;

    const float* inb = in + (size_t)b * SEQ * CIN;
    int base = t0 * CIN;
    for (int i = tid; i < 128 * 32 + DIN; i += 256) {
        int gi = base + i;
        sIn[i] = (gi < SEQ * CIN) ? inb[gi] : 0.f;
    }
    __syncthreads();

    unsigned long long acc[8][2];
#pragma unroll
    for (int i = 0; i < 8; i++) { acc[i][0] = pk2(0.f, 0.f); acc[i][1] = pk2(0.f, 0.f); }

    for (int k0 = 0; k0 < DIN; k0 += 32) {
#pragma unroll
        for (int r = 0; r < 2; r++) {
            int j = tid * 8 + r * 4;
            int kk = j >> 6, nn = j & 63;
            *(float4*)&sB[kk][nn] =
                *(const float4*)&g_wc[(size_t)(k0 + kk) * G4 + n0 + nn];
        }
        __syncthreads();
#pragma unroll
        for (int k = 0; k < 32; k++) {
            ulonglong2 bb = *(const ulonglong2*)&sB[k][tx * 4];
#pragma unroll
            for (int i = 0; i < 8; i++) {
                float a = sIn[(ty * 8 + i) * CIN + k0 + k];
                unsigned long long aa = pk2(a, a);
                fma2(acc[i][0], aa, bb.x);
                fma2(acc[i][1], aa, bb.y);
            }
        }
        __syncthreads();
    }

    float4 bias = *(const float4*)&g_bias0[n0 + tx * 4];
    int tbase = t0 + ty * 8;
    if (tbase < XT) {
#pragma unroll
        for (int nn = 0; nn < 4; nn++) {
            float bv = (nn == 0) ? bias.x : (nn == 1) ? bias.y : (nn == 2) ? bias.z : bias.w;
            float v[8];
#pragma unroll
            for (int i = 0; i < 8; i++) {
                float2 p = unpk2(acc[i][nn >> 1]);
                v[i] = ((nn & 1) ? p.y : p.x) + bv;
            }
            float* dst = &g_xpre[((size_t)b * G4 + n0 + tx * 4 + nn) * XT + tbase];
            *(float4*)(dst)     = make_float4(v[0], v[1], v[2], v[3]);
            *(float4*)(dst + 4) = make_float4(v[4], v[5], v[6], v[7]);
        }
    }
}

// ---------------------------------------------------------------------------
// Kernel 3: input preactivations for layers 1..3 (transposed output).
// ---------------------------------------------------------------------------
__global__ void __launch_bounds__(256)
gemm_ih_kernel(const float* __restrict__ w_ih,
               const float* __restrict__ b_ih,
               const float* __restrict__ b_hh) {
    __shared__ __align__(16) float sA[64 * 64];
    __shared__ __align__(16) float sB[64 * 68];

    int tid = threadIdx.x;
    int tx = tid & 15, ty = tid >> 4;
    int t0 = blockIdx.x * 64;
    int n0 = blockIdx.y * 64;
    int b  = blockIdx.z;

    unsigned long long acc[4][2];
#pragma unroll
    for (int i = 0; i < 4; i++) { acc[i][0] = pk2(0.f, 0.f); acc[i][1] = pk2(0.f, 0.f); }

    for (int kt = 0; kt < 2; kt++) {
#pragma unroll
        for (int r = 0; r < 4; r++) {
            int j = tid * 16 + r * 4;
            int row = j >> 6, col = j & 63;
            int t = t0 + row;
            float4 v = make_float4(0.f, 0.f, 0.f, 0.f);
            if (t < L_OUT)
                v = *(const float4*)&g_hseq[((size_t)b * L_OUT + t) * HID + kt * 64 + col];
            *(float4*)&sA[row * 64 + col] = v;
        }
        for (int j = tid; j < 64 * 64; j += 256) {
            int n = j >> 6, kk = j & 63;
            sB[kk * 68 + n] = w_ih[(size_t)(n0 + n) * HID + kt * 64 + kk];
        }
        __syncthreads();
#pragma unroll
        for (int k = 0; k < 64; k++) {
            ulonglong2 bb = *(const ulonglong2*)&sB[k * 68 + tx * 4];
#pragma unroll
            for (int i = 0; i < 4; i++) {
                float a = sA[(ty * 4 + i) * 64 + k];
                unsigned long long aa = pk2(a, a);
                fma2(acc[i][0], aa, bb.x);
                fma2(acc[i][1], aa, bb.y);
            }
        }
        __syncthreads();
    }

    int n = n0 + tx * 4;
    float4 bias = make_float4(b_ih[n] + b_hh[n], b_ih[n + 1] + b_hh[n + 1],
                              b_ih[n + 2] + b_hh[n + 2], b_ih[n + 3] + b_hh[n + 3]);
    int tbase = t0 + ty * 4;
    if (tbase < XT) {
#pragma unroll
        for (int nn = 0; nn < 4; nn++) {
            float bv = (nn == 0) ? bias.x : (nn == 1) ? bias.y : (nn == 2) ? bias.z : bias.w;
            float v[4];
#pragma unroll
            for (int i = 0; i < 4; i++) {
                float2 p = unpk2(acc[i][nn >> 1]);
                v[i] = ((nn & 1) ? p.y : p.x) + bv;
            }
            float* dst = &g_xpre[((size_t)b * G4 + n + nn) * XT + tbase];
            *(float4*)(dst) = make_float4(v[0], v[1], v[2], v[3]);
        }
    }
}

// ---------------------------------------------------------------------------
// Kernel 4: recurrent scan — unit-split + k-split, 512 threads, bulk h-half
// exchange (256 B) with the R6-validated expect_tx/bulk placement and the
// R3/R4-validated wait-previous-step parity formula.
//
// Thread tid: unit_local = tid>>3, sub = tid&7, gate = sub>>1 (i,f,g,o),
// kh = sub&1. CTA rank r owns global units [64r,64r+64) — all 4 gates of a
// unit are local, in 8 adjacent lanes of one warp. Each thread computes a
// 64-long half-dot: kh0 over the OWN h half (hbuf, no wait), kh1 over the
// PEER h half (land, waits for last step's bulk). Combine via shfl_down(1);
// gates gathered to sub==0 via shfl_down(2/4/6); tail computes c,h locally
// (no remote gates needed!), writes h into hbuf[t&1] (double-buffered: dot
// at t reads hbuf[(t+1)&1], so no read/write race with one sync per step).
// End of step t (tid0, after __syncthreads): expect_tx(256) on LOCAL
// bar[t&1], fence.proxy.async, 256 B bulk hbuf[t&1] -> peer land[t&1]
// signaling PEER bar[t&1]. Step t's kh1 wait: bar[(t-1)&1], parity
// ((t-1)>>1)&1; t=0 reads zero-filled land[1], no wait.
// The kh0 half-dot of step t runs concurrently with the step t-1 bulk's
// DSMEM transit — the transit is off the serial path up to ~400 cyc.
// ---------------------------------------------------------------------------
__global__ void __cluster_dims__(2, 1, 1) __launch_bounds__(512, 1)
scan_kernel(const float* __restrict__ w_hh) {
    __shared__ __align__(16) float hbuf[2][64];   // own h half (also bulk source)
    __shared__ __align__(16) float land[2][64];   // peer h half landing
    __shared__ __align__(8) unsigned long long mbars[2];

    int tid  = threadIdx.x;
    int rank = blockIdx.x & 1;
    int b    = blockIdx.x >> 1;
    int ul   = tid >> 3;          // 0..63 local unit
    int sub  = tid & 7;
    int gate = sub >> 1;          // 0:i 1:f 2:g 3:o
    int kh   = sub & 1;
    int ug   = rank * 64 + ul;    // global unit
    int row  = gate * HID + ug;   // gate row in [0,512)
    int kbase = (kh == 0) ? rank * 64 : (rank ^ 1) * 64;

    // 64 recurrent weights (this thread's k-half) -> registers as f32x2
    unsigned long long w2[32];
    const ulonglong2* wr = (const ulonglong2*)(w_hh + (size_t)row * HID + kbase);
#pragma unroll
    for (int k = 0; k < 16; k++) {
        ulonglong2 u = wr[k];
        w2[2 * k]     = u.x;
        w2[2 * k + 1] = u.y;
    }

    if (tid < 64) {
        hbuf[0][tid] = 0.f; hbuf[1][tid] = 0.f;
        land[0][tid] = 0.f; land[1][tid] = 0.f;
    }
    unsigned bar0 = smem_u32(&mbars[0]);
    unsigned bar1 = smem_u32(&mbars[1]);
    if (tid == 0) { mbar_init(bar0, 1); mbar_init(bar1, 1); }
    __syncthreads();
    cluster_barrier();   // peer mbar init + zeroed buffers visible cluster-wide

    unsigned peer = rank ^ 1;
    unsigned src0 = smem_u32(&hbuf[0][0]);
    unsigned src1 = smem_u32(&hbuf[1][0]);
    unsigned peer_l0 = mapa_rank(smem_u32(&land[0][0]), peer);
    unsigned peer_l1 = mapa_rank(smem_u32(&land[1][0]), peer);
    unsigned peer_b0 = mapa_rank(bar0, peer);
    unsigned peer_b1 = mapa_rank(bar1, peer);

    float c = 0.f;
    const size_t hrow = (size_t)b * L_OUT;
    const float* xrow_p = g_xpre + ((size_t)b * G4 + row) * XT;
    const bool tanh_gate   = (gate == 2);
    const bool lead        = (kh == 0);
    const bool tail_thread = (sub == 0);

    float4 xcur = lead ? *(const float4*)(xrow_p) : make_float4(0.f, 0.f, 0.f, 0.f);

    for (int t4 = 0; t4 < L_OUT; t4 += 4) {
        float4 xnxt = lead ? *(const float4*)(xrow_p + t4 + 4)
                           : make_float4(0.f, 0.f, 0.f, 0.f);

#pragma unroll
        for (int s = 0; s < 4; s++) {
            int t = t4 + s;
            float xp = (s == 0) ? xcur.x : (s == 1) ? xcur.y : (s == 2) ? xcur.z : xcur.w;

            // select h half: kh0 -> local hbuf (ready); kh1 -> wait for peer bulk
            const float* hb;
            if (kh == 0) {
                hb = hbuf[(t + 1) & 1];           // h(t-1), local
            } else {
                if (t > 0) {
                    int pv = t - 1;
                    mbar_wait_cluster((pv & 1) ? bar1 : bar0, (unsigned)((pv >> 1) & 1));
                }
                hb = land[(t + 1) & 1];           // land[(t-1)&1] == land[(t+1)&1]
            }

            // 64-long half-dot, 4 accumulators, packed f32x2
            unsigned long long a0 = pk2(0.f, 0.f), a1 = pk2(0.f, 0.f);
            unsigned long long a2 = pk2(0.f, 0.f), a3 = pk2(0.f, 0.f);
            const ulonglong2* h2 = (const ulonglong2*)hb;
#pragma unroll
            for (int k = 0; k < 8; k++) {
                ulonglong2 u = h2[2 * k];
                ulonglong2 v = h2[2 * k + 1];
                fma2(a0, w2[4 * k],     u.x);
                fma2(a1, w2[4 * k + 1], u.y);
                fma2(a2, w2[4 * k + 2], v.x);
                fma2(a3, w2[4 * k + 3], v.y);
            }
            float2 q0 = unpk2(a0), q1 = unpk2(a1), q2 = unpk2(a2), q3 = unpk2(a3);
            float part = ((q0.x + q0.y) + (q1.x + q1.y)) +
                         ((q2.x + q2.y) + (q3.x + q3.y));

            float other = __shfl_down_sync(0xffffffffu, part, 1);   // kh1 partner
            float pre = part + other + xp;                          // valid on kh0
            float act = tanh_gate ? fast_tanh(pre) : fast_sigmoid(pre);

            // gather gates to the unit's tail lane (sub==0): f@+2, g@+4, o@+6
            float fv = __shfl_down_sync(0xffffffffu, act, 2);
            float gv = __shfl_down_sync(0xffffffffu, act, 4);
            float ov = __shfl_down_sync(0xffffffffu, act, 6);

            if (tail_thread) {
                c = fv * c + act * gv;            // act == i gate here
                float h = ov * fast_tanh(c);
                hbuf[t & 1][ul] = h;              // local (next step's kh0 + bulk src)
                g_hseq[(hrow + t) * HID + ug] = h;
            }
            __syncthreads();   // all units' h staged; land reads of this step done

            if (tid == 0) {
                unsigned lbar = (t & 1) ? bar1 : bar0;
                mbar_expect_tx(lbar, 256);
                fence_proxy_async_cta();          // order STS -> async-proxy read
                bulk_copy_to_peer((t & 1) ? peer_l1 : peer_l0,
                                  (t & 1) ? src1 : src0,
                                  256,
                                  (t & 1) ? peer_b1 : peer_b0);
            }
        }
        xcur = xnxt;
    }
    cluster_barrier();
}

// ---------------------------------------------------------------------------
// Kernel 5: readout.
// ---------------------------------------------------------------------------
__global__ void out_kernel(const float* __restrict__ out_w,
                           const float* __restrict__ out_b,
                           float* __restrict__ out) {
    __shared__ float h[HID];
    int b = blockIdx.x;
    if (threadIdx.x < HID)
        h[threadIdx.x] = g_hseq[((size_t)b * L_OUT + (L_OUT - 1)) * HID + threadIdx.x];
    __syncthreads();
    if (threadIdx.x < LBL) {
        float acc = out_b[threadIdx.x];
        const float* wr = out_w + (size_t)threadIdx.x * HID;
#pragma unroll 8
        for (int k = 0; k < HID; k++) acc += wr[k] * h[k];
        out[(size_t)b * LBL + threadIdx.x] = acc;
    }
}

// ---------------------------------------------------------------------------
// Launch
// ---------------------------------------------------------------------------
extern "C" void kernel_launch(void* const* d_in, const int* in_sizes, int n_in,
                              void* d_out, int out_size) {
    const float* inputs    = (const float*)d_in[0];
    const float* proj_w    = (const float*)d_in[4];
    const float* proj_b    = (const float*)d_in[5];
    const float* w_ih0     = (const float*)d_in[6];
    const float* w_hh0     = (const float*)d_in[7];
    const float* b_ih0     = (const float*)d_in[8];
    const float* b_hh0     = (const float*)d_in[9];
    const float* w_ih_rest = (const float*)d_in[10];
    const float* w_hh_rest = (const float*)d_in[11];
    const float* b_ih_rest = (const float*)d_in[12];
    const float* b_hh_rest = (const float*)d_in[13];
    const float* out_w     = (const float*)d_in[14];
    const float* out_b     = (const float*)d_in[15];
    float* out = (float*)d_out;

    combine_kernel<<<dim3(DIN / 32, G4 / 32), dim3(32, 32)>>>(proj_w, w_ih0);
    bias0_kernel<<<1, G4>>>(proj_b, w_ih0, b_ih0, b_hh0);

    xpre0_kernel<<<dim3((L_OUT + 127) / 128, G4 / 64, BATCH), 256>>>(inputs);

    scan_kernel<<<BATCH * 2, 512>>>(w_hh0);   // 64 clusters x 2 CTAs

    for (int l = 0; l < 3; l++) {
        gemm_ih_kernel<<<dim3((L_OUT + 63) / 64, G4 / 64, BATCH), 256>>>(
            w_ih_rest + (size_t)l * G4 * HID,
            b_ih_rest + (size_t)l * G4,
            b_hh_rest + (size_t)l * G4);
        scan_kernel<<<BATCH * 2, 512>>>(w_hh_rest + (size_t)l * G4 * HID);
    }

    out_kernel<<<BATCH, 128>>>(out_w, out_b, out);
}

// round 9
// speedup vs baseline: 1.8698x; 1.8698x over previous
#include <cuda_runtime.h>
#include <cuda_bf16.h>
#include <cstdint>

// ---------------------------------------------------------------------------
// Problem constants
// ---------------------------------------------------------------------------
#define BATCH   64
#define SEQ     2048
#define CIN     32
#define WIN     20
#define DIN     (WIN * CIN)      // 640
#define DP      (DIN / 2)        // 320
#define HID     128
#define G4      (4 * HID)        // 512
#define L_OUT   (SEQ - WIN)      // 2028
#define XT      2032             // padded time stride for g_xpre
#define LBL     48

// ---------------------------------------------------------------------------
// Scratch (static __device__ arrays; no cudaMalloc allowed)
// ---------------------------------------------------------------------------
__device__ float g_wc[DIN * G4];                       // combined proj->ih0 weight [d][g]
__device__ float g_bias0[G4];
__device__ float g_xpre[(size_t)BATCH * G4 * XT];      // preactivations, [b][g][t] (t-major)
__device__ float g_hseq[(size_t)BATCH * L_OUT * HID];  // per-step hidden outputs [b][t][h]

// ---------------------------------------------------------------------------
// Packed fp32x2 helpers
// ---------------------------------------------------------------------------
__device__ __forceinline__ unsigned long long pk2(float x, float y) {
    unsigned long long r;
    asm("mov.b64 %0, {%1, %2};" : "=l"(r) : "f"(x), "f"(y));
    return r;
}
__device__ __forceinline__ float2 unpk2(unsigned long long v) {
    float2 r;
    asm("mov.b64 {%0, %1}, %2;" : "=f"(r.x), "=f"(r.y) : "l"(v));
    return r;
}
__device__ __forceinline__ void fma2(unsigned long long& d, unsigned long long a,
                                     unsigned long long b) {
    asm("fma.rn.f32x2 %0, %1, %2, %3;" : "=l"(d) : "l"(a), "l"(b), "l"(d));
}

// ---------------------------------------------------------------------------
// Cluster / mbarrier helpers
// ---------------------------------------------------------------------------
__device__ __forceinline__ unsigned smem_u32(const void* p) {
    return (unsigned)__cvta_generic_to_shared(p);
}
__device__ __forceinline__ unsigned mapa_rank(unsigned addr, unsigned rank) {
    unsigned r;
    asm("mapa.shared::cluster.u32 %0, %1, %2;" : "=r"(r) : "r"(addr), "r"(rank));
    return r;
}
__device__ __forceinline__ void mbar_init(unsigned addr, unsigned cnt) {
    asm volatile("mbarrier.init.shared.b64 [%0], %1;" :: "r"(addr), "r"(cnt) : "memory");
}
__device__ __forceinline__ void mbar_expect_tx(unsigned addr, unsigned bytes) {
    asm volatile("mbarrier.arrive.expect_tx.shared.b64 _, [%0], %1;"
                 :: "r"(addr), "r"(bytes) : "memory");
}
__device__ __forceinline__ void fence_proxy_async_cta() {
    asm volatile("fence.proxy.async.shared::cta;" ::: "memory");
}
__device__ __forceinline__ void bulk_copy_to_peer(unsigned dst_cluster, unsigned src_cta,
                                                  unsigned bytes, unsigned peer_mbar) {
    asm volatile(
        "cp.async.bulk.shared::cluster.shared::cta.mbarrier::complete_tx::bytes "
        "[%0], [%1], %2, [%3];"
        :: "r"(dst_cluster), "r"(src_cta), "r"(bytes), "r"(peer_mbar) : "memory");
}
__device__ __forceinline__ void mbar_wait_cluster(unsigned addr, unsigned parity) {
    asm volatile(
        "{\n\t"
        ".reg .pred P1;\n\t"
        "WAIT_%=:\n\t"
        "mbarrier.try_wait.parity.acquire.cluster.shared::cta.b64 P1, [%0], %1, 0x989680;\n\t"
        "@P1 bra.uni DONE_%=;\n\t"
        "bra.uni WAIT_%=;\n\t"
        "DONE_%=:\n\t"
        "}"
        :: "r"(addr), "r"(parity) : "memory");
}
__device__ __forceinline__ void cluster_barrier() {
    asm volatile("barrier.cluster.arrive.aligned;" ::: "memory");
    asm volatile("barrier.cluster.wait.aligned;" ::: "memory");
}

// ---------------------------------------------------------------------------
// Fast activations (fp32, ~1e-6 rel error)
// ---------------------------------------------------------------------------
__device__ __forceinline__ float fast_sigmoid(float x) {
    return 1.f / (1.f + __expf(-x));
}

// ---------------------------------------------------------------------------
// Kernel 1: fold projection into layer-0 input weight.
// ---------------------------------------------------------------------------
__global__ void combine_kernel(const float* __restrict__ proj_w,
                               const float* __restrict__ w_ih0) {
    __shared__ float sPW[32][32];
    __shared__ float sWI[32][33];
    int tx = threadIdx.x, ty = threadIdx.y;
    int d0 = blockIdx.x * 32, g0 = blockIdx.y * 32;
    float acc = 0.f;
    for (int p0 = 0; p0 < DP; p0 += 32) {
        sPW[ty][tx] = proj_w[(size_t)(p0 + ty) * DIN + d0 + tx];
        sWI[ty][tx] = w_ih0[(size_t)(g0 + ty) * DP + p0 + tx];
        __syncthreads();
#pragma unroll
        for (int p = 0; p < 32; p++) acc += sPW[p][tx] * sWI[ty][p];
        __syncthreads();
    }
    g_wc[(size_t)(d0 + tx) * G4 + g0 + ty] = acc;
}

__global__ void bias0_kernel(const float* __restrict__ proj_b,
                             const float* __restrict__ w_ih0,
                             const float* __restrict__ b_ih0,
                             const float* __restrict__ b_hh0) {
    int gidx = threadIdx.x;
    float acc = b_ih0[gidx] + b_hh0[gidx];
    const float* wr = w_ih0 + (size_t)gidx * DP;
    for (int p = 0; p < DP; p++) acc += proj_b[p] * wr[p];
    g_bias0[gidx] = acc;
}

// ---------------------------------------------------------------------------
// Kernel 2: layer-0 preactivations (implicit sliding-window GEMM).
// Output transposed: g_xpre[b][g][t].
// ---------------------------------------------------------------------------
__global__ void __launch_bounds__(256)
xpre0_kernel(const float* __restrict__ in) {
    __shared__ __align__(16) float sIn[128 * 32 + DIN];
    __shared__ __align__(16) float sB[32][64];

    int tid = threadIdx.x;
    int tx = tid & 15, ty = tid >> 4;
    int t0 = blockIdx.x * 128;
    int n0 = blockIdx.y * 64;
    int b  = blockIdx.z;

    const float* inb = in + (size_t)b * SEQ * CIN;
    int base = t0 * CIN;
    for (int i = tid; i < 128 * 32 + DIN; i += 256) {
        int gi = base + i;
        sIn[i] = (gi < SEQ * CIN) ? inb[gi] : 0.f;
    }
    __syncthreads();

    unsigned long long acc[8][2];
#pragma unroll
    for (int i = 0; i < 8; i++) { acc[i][0] = pk2(0.f, 0.f); acc[i][1] = pk2(0.f, 0.f); }

    for (int k0 = 0; k0 < DIN; k0 += 32) {
#pragma unroll
        for (int r = 0; r < 2; r++) {
            int j = tid * 8 + r * 4;
            int kk = j >> 6, nn = j & 63;
            *(float4*)&sB[kk][nn] =
                *(const float4*)&g_wc[(size_t)(k0 + kk) * G4 + n0 + nn];
        }
        __syncthreads();
#pragma unroll
        for (int k = 0; k < 32; k++) {
            ulonglong2 bb = *(const ulonglong2*)&sB[k][tx * 4];
#pragma unroll
            for (int i = 0; i < 8; i++) {
                float a = sIn[(ty * 8 + i) * CIN + k0 + k];
                unsigned long long aa = pk2(a, a);
                fma2(acc[i][0], aa, bb.x);
                fma2(acc[i][1], aa, bb.y);
            }
        }
        __syncthreads();
    }

    float4 bias = *(const float4*)&g_bias0[n0 + tx * 4];
    int tbase = t0 + ty * 8;
    if (tbase < XT) {
#pragma unroll
        for (int nn = 0; nn < 4; nn++) {
            float bv = (nn == 0) ? bias.x : (nn == 1) ? bias.y : (nn == 2) ? bias.z : bias.w;
            float v[8];
#pragma unroll
            for (int i = 0; i < 8; i++) {
                float2 p = unpk2(acc[i][nn >> 1]);
                v[i] = ((nn & 1) ? p.y : p.x) + bv;
            }
            float* dst = &g_xpre[((size_t)b * G4 + n0 + tx * 4 + nn) * XT + tbase];
            *(float4*)(dst)     = make_float4(v[0], v[1], v[2], v[3]);
            *(float4*)(dst + 4) = make_float4(v[4], v[5], v[6], v[7]);
        }
    }
}

// ---------------------------------------------------------------------------
// Kernel 3: input preactivations for layers 1..3 (transposed output).
// ---------------------------------------------------------------------------
__global__ void __launch_bounds__(256)
gemm_ih_kernel(const float* __restrict__ w_ih,
               const float* __restrict__ b_ih,
               const float* __restrict__ b_hh) {
    __shared__ __align__(16) float sA[64 * 64];
    __shared__ __align__(16) float sB[64 * 68];

    int tid = threadIdx.x;
    int tx = tid & 15, ty = tid >> 4;
    int t0 = blockIdx.x * 64;
    int n0 = blockIdx.y * 64;
    int b  = blockIdx.z;

    unsigned long long acc[4][2];
#pragma unroll
    for (int i = 0; i < 4; i++) { acc[i][0] = pk2(0.f, 0.f); acc[i][1] = pk2(0.f, 0.f); }

    for (int kt = 0; kt < 2; kt++) {
#pragma unroll
        for (int r = 0; r < 4; r++) {
            int j = tid * 16 + r * 4;
            int row = j >> 6, col = j & 63;
            int t = t0 + row;
            float4 v = make_float4(0.f, 0.f, 0.f, 0.f);
            if (t < L_OUT)
                v = *(const float4*)&g_hseq[((size_t)b * L_OUT + t) * HID + kt * 64 + col];
            *(float4*)&sA[row * 64 + col] = v;
        }
        for (int j = tid; j < 64 * 64; j += 256) {
            int n = j >> 6, kk = j & 63;
            sB[kk * 68 + n] = w_ih[(size_t)(n0 + n) * HID + kt * 64 + kk];
        }
        __syncthreads();
#pragma unroll
        for (int k = 0; k < 64; k++) {
            ulonglong2 bb = *(const ulonglong2*)&sB[k * 68 + tx * 4];
#pragma unroll
            for (int i = 0; i < 4; i++) {
                float a = sA[(ty * 4 + i) * 64 + k];
                unsigned long long aa = pk2(a, a);
                fma2(acc[i][0], aa, bb.x);
                fma2(acc[i][1], aa, bb.y);
            }
        }
        __syncthreads();
    }

    int n = n0 + tx * 4;
    float4 bias = make_float4(b_ih[n] + b_hh[n], b_ih[n + 1] + b_hh[n + 1],
                              b_ih[n + 2] + b_hh[n + 2], b_ih[n + 3] + b_hh[n + 3]);
    int tbase = t0 + ty * 4;
    if (tbase < XT) {
#pragma unroll
        for (int nn = 0; nn < 4; nn++) {
            float bv = (nn == 0) ? bias.x : (nn == 1) ? bias.y : (nn == 2) ? bias.z : bias.w;
            float v[4];
#pragma unroll
            for (int i = 0; i < 4; i++) {
                float2 p = unpk2(acc[i][nn >> 1]);
                v[i] = ((nn & 1) ? p.y : p.x) + bv;
            }
            float* dst = &g_xpre[((size_t)b * G4 + n + nn) * XT + tbase];
            *(float4*)(dst) = make_float4(v[0], v[1], v[2], v[3]);
        }
    }
}

// ---------------------------------------------------------------------------
// Kernel 4: recurrent scan — unit-split, 256 threads, CTA-UNIFORM wait.
//
// Thread tid: gate = tid&3 (i,f,g,o), ul = tid>>2 (64 local units). CTA
// rank r owns units [64r, 64r+64): all 4 gates of a unit are in 4 adjacent
// lanes of one warp -> gather via 3 shfl_down; c,h computed locally (NO
// remote gates). Only the 64-float h half (256 B) crosses the cluster.
//
// Each thread runs the full 128-dot: OWN-half columns first (local hbuf,
// ready at last sync), then a wait executed by ALL threads (warp-uniform —
// fixes R8's intra-warp divergence that serialized wait before dot), then
// the PEER half from land. The bulk transit overlaps the own-half dot.
//
// One __syncthreads per step: h double-buffered (write hbuf[t&1], dot at t
// reads hbuf[(t+1)&1]); the end-of-step barrier orders tail writes vs all
// next-step readers and vs the tid0 bulk issue.
//
// Transport/parity protocol bitwise = R8 (correctness-proven): end of step
// t: expect_tx(256) on LOCAL bar[t&1], fence.proxy.async, 256 B bulk
// hbuf[t&1] -> peer land[t&1] signaling PEER bar[t&1]. Step t waits
// bar[(t-1)&1] parity ((t-1)>>1)&1; t=0 reads zero-filled land, no wait.
// Buffer-reuse safety: our rewrite of hbuf[t&1] at t+2 follows our wait on
// peer bulk(t+1) <- peer bulk(t+1) issue <- peer wait on our bulk(t) <-
// our bulk(t) source fully read. land overwrite chain symmetric.
// ---------------------------------------------------------------------------
__global__ void __cluster_dims__(2, 1, 1) __launch_bounds__(256, 1)
scan_kernel(const float* __restrict__ w_hh) {
    __shared__ __align__(16) float hbuf[2][64];   // own h half (bulk source)
    __shared__ __align__(16) float land[2][64];   // peer h half landing
    __shared__ __align__(8) unsigned long long mbars[2];

    int tid  = threadIdx.x;
    int rank = blockIdx.x & 1;
    int b    = blockIdx.x >> 1;
    int gate = tid & 3;           // 0:i 1:f 2:g 3:o
    int ul   = tid >> 2;          // 0..63 local unit
    int ug   = rank * 64 + ul;    // global unit
    int row  = gate * HID + ug;   // gate row in [0,512)
    int kown  = rank * 64;
    int kpeer = (rank ^ 1) * 64;

    // full 128 recurrent weights, split own-half / peer-half, as f32x2 pairs
    unsigned long long wown[32], wpeer[32];
    {
        const ulonglong2* wr = (const ulonglong2*)(w_hh + (size_t)row * HID + kown);
#pragma unroll
        for (int k = 0; k < 16; k++) {
            ulonglong2 u = wr[k];
            wown[2 * k]     = u.x;
            wown[2 * k + 1] = u.y;
        }
        const ulonglong2* wp = (const ulonglong2*)(w_hh + (size_t)row * HID + kpeer);
#pragma unroll
        for (int k = 0; k < 16; k++) {
            ulonglong2 u = wp[k];
            wpeer[2 * k]     = u.x;
            wpeer[2 * k + 1] = u.y;
        }
    }

    if (tid < 64) {
        hbuf[0][tid] = 0.f; hbuf[1][tid] = 0.f;
        land[0][tid] = 0.f; land[1][tid] = 0.f;
    }
    unsigned bar0 = smem_u32(&mbars[0]);
    unsigned bar1 = smem_u32(&mbars[1]);
    if (tid == 0) { mbar_init(bar0, 1); mbar_init(bar1, 1); }
    __syncthreads();
    cluster_barrier();   // peer mbar init + zeroed buffers visible cluster-wide

    unsigned peer = rank ^ 1;
    unsigned src0 = smem_u32(&hbuf[0][0]);
    unsigned src1 = smem_u32(&hbuf[1][0]);
    unsigned peer_l0 = mapa_rank(smem_u32(&land[0][0]), peer);
    unsigned peer_l1 = mapa_rank(smem_u32(&land[1][0]), peer);
    unsigned peer_b0 = mapa_rank(bar0, peer);
    unsigned peer_b1 = mapa_rank(bar1, peer);

    float c = 0.f;
    const size_t hrow = (size_t)b * L_OUT;
    const float* xrow_p = g_xpre + ((size_t)b * G4 + row) * XT;

    // branchless activation constants: sigmoid (i,f,o) / tanh (g)
    const float s_ = (gate == 2) ? 2.f : 1.f;
    const float m_ = (gate == 2) ? 2.f : 1.f;
    const float a_ = (gate == 2) ? -1.f : 0.f;
    const bool  tail = (gate == 0);

    float4 xcur = *(const float4*)(xrow_p);

    for (int t4 = 0; t4 < L_OUT; t4 += 4) {
        float4 xnxt = *(const float4*)(xrow_p + t4 + 4);

#pragma unroll
        for (int s = 0; s < 4; s++) {
            int t = t4 + s;
            float xp = (s == 0) ? xcur.x : (s == 1) ? xcur.y : (s == 2) ? xcur.z : xcur.w;

            unsigned long long a0 = pk2(0.f, 0.f), a1 = pk2(0.f, 0.f);
            unsigned long long a2 = pk2(0.f, 0.f), a3 = pk2(0.f, 0.f);

            // own half: local h, ready since last sync — overlaps peer bulk transit
            {
                const ulonglong2* h2 = (const ulonglong2*)hbuf[(t + 1) & 1];
#pragma unroll
                for (int k = 0; k < 8; k++) {
                    ulonglong2 u = h2[2 * k];
                    ulonglong2 v = h2[2 * k + 1];
                    fma2(a0, wown[4 * k],     u.x);
                    fma2(a1, wown[4 * k + 1], u.y);
                    fma2(a2, wown[4 * k + 2], v.x);
                    fma2(a3, wown[4 * k + 3], v.y);
                }
            }

            // CTA-uniform wait for peer's h half (bulk issued at end of t-1)
            if (t > 0) {
                int pv = t - 1;
                mbar_wait_cluster((pv & 1) ? bar1 : bar0, (unsigned)((pv >> 1) & 1));
            }

            // peer half from landing buffer
            {
                const ulonglong2* h2 = (const ulonglong2*)land[(t + 1) & 1];
#pragma unroll
                for (int k = 0; k < 8; k++) {
                    ulonglong2 u = h2[2 * k];
                    ulonglong2 v = h2[2 * k + 1];
                    fma2(a0, wpeer[4 * k],     u.x);
                    fma2(a1, wpeer[4 * k + 1], u.y);
                    fma2(a2, wpeer[4 * k + 2], v.x);
                    fma2(a3, wpeer[4 * k + 3], v.y);
                }
            }

            float2 q0 = unpk2(a0), q1 = unpk2(a1), q2 = unpk2(a2), q3 = unpk2(a3);
            float pre = (((q0.x + q0.y) + (q1.x + q1.y)) +
                         ((q2.x + q2.y) + (q3.x + q3.y))) + xp;
            float act = fmaf(m_, fast_sigmoid(s_ * pre), a_);

            // gather f,g,o to the unit's i-lane (gate 0)
            float fv = __shfl_down_sync(0xffffffffu, act, 1);
            float gv = __shfl_down_sync(0xffffffffu, act, 2);
            float ov = __shfl_down_sync(0xffffffffu, act, 3);

            if (tail) {
                c = fv * c + act * gv;                              // act == i
                float tc = fmaf(2.f, fast_sigmoid(2.f * c), -1.f);  // tanh(c)
                float h  = ov * tc;
                hbuf[t & 1][ul] = h;
                g_hseq[(hrow + t) * HID + ug] = h;
            }
            __syncthreads();   // h(t) staged; land/hbuf reads of this step done

            if (tid == 0) {
                unsigned lbar = (t & 1) ? bar1 : bar0;
                mbar_expect_tx(lbar, 256);
                fence_proxy_async_cta();          // order STS -> async-proxy read
                bulk_copy_to_peer((t & 1) ? peer_l1 : peer_l0,
                                  (t & 1) ? src1 : src0,
                                  256,
                                  (t & 1) ? peer_b1 : peer_b0);
            }
        }
        xcur = xnxt;
    }
    cluster_barrier();
}

// ---------------------------------------------------------------------------
// Kernel 5: readout.
// ---------------------------------------------------------------------------
__global__ void out_kernel(const float* __restrict__ out_w,
                           const float* __restrict__ out_b,
                           float* __restrict__ out) {
    __shared__ float h[HID];
    int b = blockIdx.x;
    if (threadIdx.x < HID)
        h[threadIdx.x] = g_hseq[((size_t)b * L_OUT + (L_OUT - 1)) * HID + threadIdx.x];
    __syncthreads();
    if (threadIdx.x < LBL) {
        float acc = out_b[threadIdx.x];
        const float* wr = out_w + (size_t)threadIdx.x * HID;
#pragma unroll 8
        for (int k = 0; k < HID; k++) acc += wr[k] * h[k];
        out[(size_t)b * LBL + threadIdx.x] = acc;
    }
}

// ---------------------------------------------------------------------------
// Launch
// ---------------------------------------------------------------------------
extern "C" void kernel_launch(void* const* d_in, const int* in_sizes, int n_in,
                              void* d_out, int out_size) {
    const float* inputs    = (const float*)d_in[0];
    const float* proj_w    = (const float*)d_in[4];
    const float* proj_b    = (const float*)d_in[5];
    const float* w_ih0     = (const float*)d_in[6];
    const float* w_hh0     = (const float*)d_in[7];
    const float* b_ih0     = (const float*)d_in[8];
    const float* b_hh0     = (const float*)d_in[9];
    const float* w_ih_rest = (const float*)d_in[10];
    const float* w_hh_rest = (const float*)d_in[11];
    const float* b_ih_rest = (const float*)d_in[12];
    const float* b_hh_rest = (const float*)d_in[13];
    const float* out_w     = (const float*)d_in[14];
    const float* out_b     = (const float*)d_in[15];
    float* out = (float*)d_out;

    combine_kernel<<<dim3(DIN / 32, G4 / 32), dim3(32, 32)>>>(proj_w, w_ih0);
    bias0_kernel<<<1, G4>>>(proj_b, w_ih0, b_ih0, b_hh0);

    xpre0_kernel<<<dim3((L_OUT + 127) / 128, G4 / 64, BATCH), 256>>>(inputs);

    scan_kernel<<<BATCH * 2, 256>>>(w_hh0);   // 64 clusters x 2 CTAs

    for (int l = 0; l < 3; l++) {
        gemm_ih_kernel<<<dim3((L_OUT + 63) / 64, G4 / 64, BATCH), 256>>>(
            w_ih_rest + (size_t)l * G4 * HID,
            b_ih_rest + (size_t)l * G4,
            b_hh_rest + (size_t)l * G4);
        scan_kernel<<<BATCH * 2, 256>>>(w_hh_rest + (size_t)l * G4 * HID);
    }

    out_kernel<<<BATCH, 128>>>(out_w, out_b, out);
}

// round 10
// speedup vs baseline: 1.9017x; 1.0171x over previous
#include <cuda_runtime.h>
#include <cuda_bf16.h>
#include <cstdint>

// ---------------------------------------------------------------------------
// Problem constants
// ---------------------------------------------------------------------------
#define BATCH   64
#define SEQ     2048
#define CIN     32
#define WIN     20
#define DIN     (WIN * CIN)      // 640
#define DP      (DIN / 2)        // 320
#define HID     128
#define G4      (4 * HID)        // 512
#define L_OUT   (SEQ - WIN)      // 2028
#define XT      2032             // padded time stride for g_xpre
#define LBL     48

// ---------------------------------------------------------------------------
// Scratch (static __device__ arrays; no cudaMalloc allowed)
// ---------------------------------------------------------------------------
__device__ float g_wc[DIN * G4];                       // combined proj->ih0 weight [d][g]
__device__ float g_bias0[G4];
__device__ float g_xpre[(size_t)BATCH * G4 * XT];      // preactivations, [b][g][t] (t-major)
__device__ float g_hseq[(size_t)BATCH * L_OUT * HID];  // per-step hidden outputs [b][t][h]

// ---------------------------------------------------------------------------
// Packed fp32x2 helpers
// ---------------------------------------------------------------------------
__device__ __forceinline__ unsigned long long pk2(float x, float y) {
    unsigned long long r;
    asm("mov.b64 %0, {%1, %2};" : "=l"(r) : "f"(x), "f"(y));
    return r;
}
__device__ __forceinline__ float2 unpk2(unsigned long long v) {
    float2 r;
    asm("mov.b64 {%0, %1}, %2;" : "=f"(r.x), "=f"(r.y) : "l"(v));
    return r;
}
__device__ __forceinline__ void fma2(unsigned long long& d, unsigned long long a,
                                     unsigned long long b) {
    asm("fma.rn.f32x2 %0, %1, %2, %3;" : "=l"(d) : "l"(a), "l"(b), "l"(d));
}

// ---------------------------------------------------------------------------
// Cluster / mbarrier helpers
// ---------------------------------------------------------------------------
__device__ __forceinline__ unsigned smem_u32(const void* p) {
    return (unsigned)__cvta_generic_to_shared(p);
}
__device__ __forceinline__ unsigned mapa_rank(unsigned addr, unsigned rank) {
    unsigned r;
    asm("mapa.shared::cluster.u32 %0, %1, %2;" : "=r"(r) : "r"(addr), "r"(rank));
    return r;
}
__device__ __forceinline__ void mbar_init(unsigned addr, unsigned cnt) {
    asm volatile("mbarrier.init.shared.b64 [%0], %1;" :: "r"(addr), "r"(cnt) : "memory");
}
__device__ __forceinline__ void mbar_expect_tx(unsigned addr, unsigned bytes) {
    asm volatile("mbarrier.arrive.expect_tx.shared.b64 _, [%0], %1;"
                 :: "r"(addr), "r"(bytes) : "memory");
}
// Remote SMEM store with mbarrier tx-completion (4 bytes per store).
__device__ __forceinline__ void st_async_f32(unsigned raddr, float v, unsigned rmbar) {
    asm volatile(
        "st.async.shared::cluster.mbarrier::complete_tx::bytes.f32 [%0], %1, [%2];"
        :: "r"(raddr), "f"(v), "r"(rmbar) : "memory");
}
__device__ __forceinline__ void mbar_wait_cluster(unsigned addr, unsigned parity) {
    asm volatile(
        "{\n\t"
        ".reg .pred P1;\n\t"
        "WAIT_%=:\n\t"
        "mbarrier.try_wait.parity.acquire.cluster.shared::cta.b64 P1, [%0], %1, 0x989680;\n\t"
        "@P1 bra.uni DONE_%=;\n\t"
        "bra.uni WAIT_%=;\n\t"
        "DONE_%=:\n\t"
        "}"
        :: "r"(addr), "r"(parity) : "memory");
}
__device__ __forceinline__ void cluster_barrier() {
    asm volatile("barrier.cluster.arrive.aligned;" ::: "memory");
    asm volatile("barrier.cluster.wait.aligned;" ::: "memory");
}

// ---------------------------------------------------------------------------
// Fast activations (fp32, ~1e-6 rel error)
// ---------------------------------------------------------------------------
__device__ __forceinline__ float fast_sigmoid(float x) {
    return 1.f / (1.f + __expf(-x));
}

// ---------------------------------------------------------------------------
// Kernel 1: fold projection into layer-0 input weight.
// ---------------------------------------------------------------------------
__global__ void combine_kernel(const float* __restrict__ proj_w,
                               const float* __restrict__ w_ih0) {
    __shared__ float sPW[32][32];
    __shared__ float sWI[32][33];
    int tx = threadIdx.x, ty = threadIdx.y;
    int d0 = blockIdx.x * 32, g0 = blockIdx.y * 32;
    float acc = 0.f;
    for (int p0 = 0; p0 < DP; p0 += 32) {
        sPW[ty][tx] = proj_w[(size_t)(p0 + ty) * DIN + d0 + tx];
        sWI[ty][tx] = w_ih0[(size_t)(g0 + ty) * DP + p0 + tx];
        __syncthreads();
#pragma unroll
        for (int p = 0; p < 32; p++) acc += sPW[p][tx] * sWI[ty][p];
        __syncthreads();
    }
    g_wc[(size_t)(d0 + tx) * G4 + g0 + ty] = acc;
}

__global__ void bias0_kernel(const float* __restrict__ proj_b,
                             const float* __restrict__ w_ih0,
                             const float* __restrict__ b_ih0,
                             const float* __restrict__ b_hh0) {
    int gidx = threadIdx.x;
    float acc = b_ih0[gidx] + b_hh0[gidx];
    const float* wr = w_ih0 + (size_t)gidx * DP;
    for (int p = 0; p < DP; p++) acc += proj_b[p] * wr[p];
    g_bias0[gidx] = acc;
}

// ---------------------------------------------------------------------------
// Kernel 2: layer-0 preactivations (implicit sliding-window GEMM).
// Output transposed: g_xpre[b][g][t].
// ---------------------------------------------------------------------------
__global__ void __launch_bounds__(256)
xpre0_kernel(const float* __restrict__ in) {
    __shared__ __align__(16) float sIn[128 * 32 + DIN];
    __shared__ __align__(16) float sB[32][64];

    int tid = threadIdx.x;
    int tx = tid & 15, ty = tid >> 4;
    int t0 = blockIdx.x * 128;
    int n0 = blockIdx.y * 64;
    int b  = blockIdx.z;

    const float* inb = in + (size_t)b * SEQ * CIN;
    int base = t0 * CIN;
    for (int i = tid; i < 128 * 32 + DIN; i += 256) {
        int gi = base + i;
        sIn[i] = (gi < SEQ * CIN) ? inb[gi] : 0.f;
    }
    __syncthreads();

    unsigned long long acc[8][2];
#pragma unroll
    for (int i = 0; i < 8; i++) { acc[i][0] = pk2(0.f, 0.f); acc[i][1] = pk2(0.f, 0.f); }

    for (int k0 = 0; k0 < DIN; k0 += 32) {
#pragma unroll
        for (int r = 0; r < 2; r++) {
            int j = tid * 8 + r * 4;
            int kk = j >> 6, nn = j & 63;
            *(float4*)&sB[kk][nn] =
                *(const float4*)&g_wc[(size_t)(k0 + kk) * G4 + n0 + nn];
        }
        __syncthreads();
#pragma unroll
        for (int k = 0; k < 32; k++) {
            ulonglong2 bb = *(const ulonglong2*)&sB[k][tx * 4];
#pragma unroll
            for (int i = 0; i < 8; i++) {
                float a = sIn[(ty * 8 + i) * CIN + k0 + k];
                unsigned long long aa = pk2(a, a);
                fma2(acc[i][0], aa, bb.x);
                fma2(acc[i][1], aa, bb.y);
            }
        }
        __syncthreads();
    }

    float4 bias = *(const float4*)&g_bias0[n0 + tx * 4];
    int tbase = t0 + ty * 8;
    if (tbase < XT) {
#pragma unroll
        for (int nn = 0; nn < 4; nn++) {
            float bv = (nn == 0) ? bias.x : (nn == 1) ? bias.y : (nn == 2) ? bias.z : bias.w;
            float v[8];
#pragma unroll
            for (int i = 0; i < 8; i++) {
                float2 p = unpk2(acc[i][nn >> 1]);
                v[i] = ((nn & 1) ? p.y : p.x) + bv;
            }
            float* dst = &g_xpre[((size_t)b * G4 + n0 + tx * 4 + nn) * XT + tbase];
            *(float4*)(dst)     = make_float4(v[0], v[1], v[2], v[3]);
            *(float4*)(dst + 4) = make_float4(v[4], v[5], v[6], v[7]);
        }
    }
}

// ---------------------------------------------------------------------------
// Kernel 3: input preactivations for layers 1..3 (transposed output).
// ---------------------------------------------------------------------------
__global__ void __launch_bounds__(256)
gemm_ih_kernel(const float* __restrict__ w_ih,
               const float* __restrict__ b_ih,
               const float* __restrict__ b_hh) {
    __shared__ __align__(16) float sA[64 * 64];
    __shared__ __align__(16) float sB[64 * 68];

    int tid = threadIdx.x;
    int tx = tid & 15, ty = tid >> 4;
    int t0 = blockIdx.x * 64;
    int n0 = blockIdx.y * 64;
    int b  = blockIdx.z;

    unsigned long long acc[4][2];
#pragma unroll
    for (int i = 0; i < 4; i++) { acc[i][0] = pk2(0.f, 0.f); acc[i][1] = pk2(0.f, 0.f); }

    for (int kt = 0; kt < 2; kt++) {
#pragma unroll
        for (int r = 0; r < 4; r++) {
            int j = tid * 16 + r * 4;
            int row = j >> 6, col = j & 63;
            int t = t0 + row;
            float4 v = make_float4(0.f, 0.f, 0.f, 0.f);
            if (t < L_OUT)
                v = *(const float4*)&g_hseq[((size_t)b * L_OUT + t) * HID + kt * 64 + col];
            *(float4*)&sA[row * 64 + col] = v;
        }
        for (int j = tid; j < 64 * 64; j += 256) {
            int n = j >> 6, kk = j & 63;
            sB[kk * 68 + n] = w_ih[(size_t)(n0 + n) * HID + kt * 64 + kk];
        }
        __syncthreads();
#pragma unroll
        for (int k = 0; k < 64; k++) {
            ulonglong2 bb = *(const ulonglong2*)&sB[k * 68 + tx * 4];
#pragma unroll
            for (int i = 0; i < 4; i++) {
                float a = sA[(ty * 4 + i) * 64 + k];
                unsigned long long aa = pk2(a, a);
                fma2(acc[i][0], aa, bb.x);
                fma2(acc[i][1], aa, bb.y);
            }
        }
        __syncthreads();
    }

    int n = n0 + tx * 4;
    float4 bias = make_float4(b_ih[n] + b_hh[n], b_ih[n + 1] + b_hh[n + 1],
                              b_ih[n + 2] + b_hh[n + 2], b_ih[n + 3] + b_hh[n + 3]);
    int tbase = t0 + ty * 4;
    if (tbase < XT) {
#pragma unroll
        for (int nn = 0; nn < 4; nn++) {
            float bv = (nn == 0) ? bias.x : (nn == 1) ? bias.y : (nn == 2) ? bias.z : bias.w;
            float v[4];
#pragma unroll
            for (int i = 0; i < 4; i++) {
                float2 p = unpk2(acc[i][nn >> 1]);
                v[i] = ((nn & 1) ? p.y : p.x) + bv;
            }
            float* dst = &g_xpre[((size_t)b * G4 + n + nn) * XT + tbase];
            *(float4*)(dst) = make_float4(v[0], v[1], v[2], v[3]);
        }
    }
}

// ---------------------------------------------------------------------------
// Kernel 4: recurrent scan — R9 structure (unit-split, CTA-uniform wait),
// with the 256 B bulk replaced by 64 direct st.async stores issued by the
// tail threads the moment each unit's h is ready (before the end-of-step
// barrier). Receiver arms its bar[t&1] with expect_tx(256) at step start
// (tid0); tx-before-expect is legal (signed accounting). This starts the
// DSMEM transit ~100-150 cyc earlier and removes the proxy fence + tid0
// bulk issue from the serial path.
//
// Parity schedule unchanged (R6/R8/R9-proven): step t's stores complete
// peer bar[t&1]; consumer waits at step t on bar[(t-1)&1] parity
// ((t-1)>>1)&1; t=0 reads zero-filled land, no wait.
//
// WAR safety: our step-t stores into peer land[t&1] are issued after our
// step-t wait (for peer h(t-1)); that wait required ALL 64 peer units'
// stores, each issued after its own warp's step-(t-1) land reads — so all
// peer reads of land[t&1] (their step t-1) precede our overwrite. Local
// hbuf visibility still via the one end-of-step __syncthreads. Last-step
// stores/arms skipped (nothing in flight at exit).
// ---------------------------------------------------------------------------
__global__ void __cluster_dims__(2, 1, 1) __launch_bounds__(256, 1)
scan_kernel(const float* __restrict__ w_hh) {
    __shared__ __align__(16) float hbuf[2][64];   // own h half
    __shared__ __align__(16) float land[2][64];   // peer h half landing
    __shared__ __align__(8) unsigned long long mbars[2];

    int tid  = threadIdx.x;
    int rank = blockIdx.x & 1;
    int b    = blockIdx.x >> 1;
    int gate = tid & 3;           // 0:i 1:f 2:g 3:o
    int ul   = tid >> 2;          // 0..63 local unit
    int ug   = rank * 64 + ul;    // global unit
    int row  = gate * HID + ug;   // gate row in [0,512)
    int kown  = rank * 64;
    int kpeer = (rank ^ 1) * 64;

    // full 128 recurrent weights, split own-half / peer-half, as f32x2 pairs
    unsigned long long wown[32], wpeer[32];
    {
        const ulonglong2* wr = (const ulonglong2*)(w_hh + (size_t)row * HID + kown);
#pragma unroll
        for (int k = 0; k < 16; k++) {
            ulonglong2 u = wr[k];
            wown[2 * k]     = u.x;
            wown[2 * k + 1] = u.y;
        }
        const ulonglong2* wp = (const ulonglong2*)(w_hh + (size_t)row * HID + kpeer);
#pragma unroll
        for (int k = 0; k < 16; k++) {
            ulonglong2 u = wp[k];
            wpeer[2 * k]     = u.x;
            wpeer[2 * k + 1] = u.y;
        }
    }

    if (tid < 64) {
        hbuf[0][tid] = 0.f; hbuf[1][tid] = 0.f;
        land[0][tid] = 0.f; land[1][tid] = 0.f;
    }
    unsigned bar0 = smem_u32(&mbars[0]);
    unsigned bar1 = smem_u32(&mbars[1]);
    if (tid == 0) { mbar_init(bar0, 1); mbar_init(bar1, 1); }
    __syncthreads();
    cluster_barrier();   // peer mbar init + zeroed buffers visible cluster-wide

    unsigned peer = rank ^ 1;
    unsigned peer_l0 = mapa_rank(smem_u32(&land[0][0]), peer) + (unsigned)ul * 4u;
    unsigned peer_l1 = mapa_rank(smem_u32(&land[1][0]), peer) + (unsigned)ul * 4u;
    unsigned peer_b0 = mapa_rank(bar0, peer);
    unsigned peer_b1 = mapa_rank(bar1, peer);

    float c = 0.f;
    const size_t hrow = (size_t)b * L_OUT;
    const float* xrow_p = g_xpre + ((size_t)b * G4 + row) * XT;

    // branchless activation constants: sigmoid (i,f,o) / tanh (g)
    const float s_ = (gate == 2) ? 2.f : 1.f;
    const float m_ = (gate == 2) ? 2.f : 1.f;
    const float a_ = (gate == 2) ? -1.f : 0.f;
    const bool  tail = (gate == 0);

    float4 xcur = *(const float4*)(xrow_p);

    for (int t4 = 0; t4 < L_OUT; t4 += 4) {
        float4 xnxt = *(const float4*)(xrow_p + t4 + 4);

#pragma unroll
        for (int s = 0; s < 4; s++) {
            int t = t4 + s;
            float xp = (s == 0) ? xcur.x : (s == 1) ? xcur.y : (s == 2) ? xcur.z : xcur.w;

            // arm local bar[t&1] to receive peer h(t) (read at step t+1)
            if (tid == 0 && t + 1 < L_OUT)
                mbar_expect_tx((t & 1) ? bar1 : bar0, 256);

            unsigned long long a0 = pk2(0.f, 0.f), a1 = pk2(0.f, 0.f);
            unsigned long long a2 = pk2(0.f, 0.f), a3 = pk2(0.f, 0.f);

            // own half: local h, ready since last sync — overlaps peer transit
            {
                const ulonglong2* h2 = (const ulonglong2*)hbuf[(t + 1) & 1];
#pragma unroll
                for (int k = 0; k < 8; k++) {
                    ulonglong2 u = h2[2 * k];
                    ulonglong2 v = h2[2 * k + 1];
                    fma2(a0, wown[4 * k],     u.x);
                    fma2(a1, wown[4 * k + 1], u.y);
                    fma2(a2, wown[4 * k + 2], v.x);
                    fma2(a3, wown[4 * k + 3], v.y);
                }
            }

            // CTA-uniform wait for peer's h(t-1) (stores issued during peer step t-1)
            if (t > 0) {
                int pv = t - 1;
                mbar_wait_cluster((pv & 1) ? bar1 : bar0, (unsigned)((pv >> 1) & 1));
            }

            // peer half from landing buffer
            {
                const ulonglong2* h2 = (const ulonglong2*)land[(t + 1) & 1];
#pragma unroll
                for (int k = 0; k < 8; k++) {
                    ulonglong2 u = h2[2 * k];
                    ulonglong2 v = h2[2 * k + 1];
                    fma2(a0, wpeer[4 * k],     u.x);
                    fma2(a1, wpeer[4 * k + 1], u.y);
                    fma2(a2, wpeer[4 * k + 2], v.x);
                    fma2(a3, wpeer[4 * k + 3], v.y);
                }
            }

            float2 q0 = unpk2(a0), q1 = unpk2(a1), q2 = unpk2(a2), q3 = unpk2(a3);
            float pre = (((q0.x + q0.y) + (q1.x + q1.y)) +
                         ((q2.x + q2.y) + (q3.x + q3.y))) + xp;
            float act = fmaf(m_, fast_sigmoid(s_ * pre), a_);

            // gather f,g,o to the unit's i-lane (gate 0)
            float fv = __shfl_down_sync(0xffffffffu, act, 1);
            float gv = __shfl_down_sync(0xffffffffu, act, 2);
            float ov = __shfl_down_sync(0xffffffffu, act, 3);

            if (tail) {
                c = fv * c + act * gv;                              // act == i
                float tc = fmaf(2.f, fast_sigmoid(2.f * c), -1.f);  // tanh(c)
                float h  = ov * tc;
                if (t + 1 < L_OUT)                                  // remote, ASAP
                    st_async_f32((t & 1) ? peer_l1 : peer_l0, h,
                                 (t & 1) ? peer_b1 : peer_b0);
                hbuf[t & 1][ul] = h;                                // local
                g_hseq[(hrow + t) * HID + ug] = h;
            }
            __syncthreads();   // h(t) staged locally; land/hbuf reads done
        }
        xcur = xnxt;
    }
    cluster_barrier();
}

// ---------------------------------------------------------------------------
// Kernel 5: readout.
// ---------------------------------------------------------------------------
__global__ void out_kernel(const float* __restrict__ out_w,
                           const float* __restrict__ out_b,
                           float* __restrict__ out) {
    __shared__ float h[HID];
    int b = blockIdx.x;
    if (threadIdx.x < HID)
        h[threadIdx.x] = g_hseq[((size_t)b * L_OUT + (L_OUT - 1)) * HID + threadIdx.x];
    __syncthreads();
    if (threadIdx.x < LBL) {
        float acc = out_b[threadIdx.x];
        const float* wr = out_w + (size_t)threadIdx.x * HID;
#pragma unroll 8
        for (int k = 0; k < HID; k++) acc += wr[k] * h[k];
        out[(size_t)b * LBL + threadIdx.x] = acc;
    }
}

// ---------------------------------------------------------------------------
// Launch
// ---------------------------------------------------------------------------
extern "C" void kernel_launch(void* const* d_in, const int* in_sizes, int n_in,
                              void* d_out, int out_size) {
    const float* inputs    = (const float*)d_in[0];
    const float* proj_w    = (const float*)d_in[4];
    const float* proj_b    = (const float*)d_in[5];
    const float* w_ih0     = (const float*)d_in[6];
    const float* w_hh0     = (const float*)d_in[7];
    const float* b_ih0     = (const float*)d_in[8];
    const float* b_hh0     = (const float*)d_in[9];
    const float* w_ih_rest = (const float*)d_in[10];
    const float* w_hh_rest = (const float*)d_in[11];
    const float* b_ih_rest = (const float*)d_in[12];
    const float* b_hh_rest = (const float*)d_in[13];
    const float* out_w     = (const float*)d_in[14];
    const float* out_b     = (const float*)d_in[15];
    float* out = (float*)d_out;

    combine_kernel<<<dim3(DIN / 32, G4 / 32), dim3(32, 32)>>>(proj_w, w_ih0);
    bias0_kernel<<<1, G4>>>(proj_b, w_ih0, b_ih0, b_hh0);

    xpre0_kernel<<<dim3((L_OUT + 127) / 128, G4 / 64, BATCH), 256>>>(inputs);

    scan_kernel<<<BATCH * 2, 256>>>(w_hh0);   // 64 clusters x 2 CTAs

    for (int l = 0; l < 3; l++) {
        gemm_ih_kernel<<<dim3((L_OUT + 63) / 64, G4 / 64, BATCH), 256>>>(
            w_ih_rest + (size_t)l * G4 * HID,
            b_ih_rest + (size_t)l * G4,
            b_hh_rest + (size_t)l * G4);
        scan_kernel<<<BATCH * 2, 256>>>(w_hh_rest + (size_t)l * G4 * HID);
    }

    out_kernel<<<BATCH, 128>>>(out_w, out_b, out);
}

// round 11
// speedup vs baseline: 2.3863x; 1.2548x over previous
#include <cuda_runtime.h>
#include <cuda_bf16.h>
#include <cstdint>

// ---------------------------------------------------------------------------
// Problem constants
// ---------------------------------------------------------------------------
#define BATCH   64
#define SEQ     2048
#define CIN     32
#define WIN     20
#define DIN     (WIN * CIN)      // 640
#define DP      (DIN / 2)        // 320
#define HID     128
#define G4      (4 * HID)        // 512
#define L_OUT   (SEQ - WIN)      // 2028
#define XT      2032             // padded time stride for g_xpre
#define LBL     48

// ---------------------------------------------------------------------------
// Scratch (static __device__ arrays; no cudaMalloc allowed)
// ---------------------------------------------------------------------------
__device__ float g_wc[DIN * G4];                       // combined proj->ih0 weight [k][g], tf32-rounded
__device__ float g_bias0[G4];
__device__ float g_xpre[(size_t)BATCH * G4 * XT];      // preactivations, [b][g][t] (t-major)
__device__ float g_hseq[(size_t)BATCH * L_OUT * HID];  // per-step hidden outputs [b][t][h]

// ---------------------------------------------------------------------------
// Packed fp32x2 helpers (scan only)
// ---------------------------------------------------------------------------
__device__ __forceinline__ unsigned long long pk2(float x, float y) {
    unsigned long long r;
    asm("mov.b64 %0, {%1, %2};" : "=l"(r) : "f"(x), "f"(y));
    return r;
}
__device__ __forceinline__ float2 unpk2(unsigned long long v) {
    float2 r;
    asm("mov.b64 {%0, %1}, %2;" : "=f"(r.x), "=f"(r.y) : "l"(v));
    return r;
}
__device__ __forceinline__ void fma2(unsigned long long& d, unsigned long long a,
                                     unsigned long long b) {
    asm("fma.rn.f32x2 %0, %1, %2, %3;" : "=l"(d) : "l"(a), "l"(b), "l"(d));
}

// ---------------------------------------------------------------------------
// tf32 helpers
// ---------------------------------------------------------------------------
__device__ __forceinline__ float to_tf32(float x) {
    unsigned u;
    asm("cvt.rna.tf32.f32 %0, %1;" : "=r"(u) : "f"(x));
    return __uint_as_float(u);
}
// D(16x8,f32) += A(16x8 tf32, row) * B(8x8 tf32, col)
__device__ __forceinline__ void mma_tf32(float* d, const unsigned* a, const unsigned* b) {
    asm volatile(
        "mma.sync.aligned.m16n8k8.row.col.f32.tf32.tf32.f32 "
        "{%0,%1,%2,%3}, {%4,%5,%6,%7}, {%8,%9}, {%0,%1,%2,%3};"
        : "+f"(d[0]), "+f"(d[1]), "+f"(d[2]), "+f"(d[3])
        : "r"(a[0]), "r"(a[1]), "r"(a[2]), "r"(a[3]), "r"(b[0]), "r"(b[1]));
}

// ---------------------------------------------------------------------------
// Cluster / mbarrier helpers
// ---------------------------------------------------------------------------
__device__ __forceinline__ unsigned smem_u32(const void* p) {
    return (unsigned)__cvta_generic_to_shared(p);
}
__device__ __forceinline__ unsigned mapa_rank(unsigned addr, unsigned rank) {
    unsigned r;
    asm("mapa.shared::cluster.u32 %0, %1, %2;" : "=r"(r) : "r"(addr), "r"(rank));
    return r;
}
__device__ __forceinline__ void mbar_init(unsigned addr, unsigned cnt) {
    asm volatile("mbarrier.init.shared.b64 [%0], %1;" :: "r"(addr), "r"(cnt) : "memory");
}
__device__ __forceinline__ void mbar_expect_tx(unsigned addr, unsigned bytes) {
    asm volatile("mbarrier.arrive.expect_tx.shared.b64 _, [%0], %1;"
                 :: "r"(addr), "r"(bytes) : "memory");
}
__device__ __forceinline__ void st_async_f32(unsigned raddr, float v, unsigned rmbar) {
    asm volatile(
        "st.async.shared::cluster.mbarrier::complete_tx::bytes.f32 [%0], %1, [%2];"
        :: "r"(raddr), "f"(v), "r"(rmbar) : "memory");
}
__device__ __forceinline__ void mbar_wait_cluster(unsigned addr, unsigned parity) {
    asm volatile(
        "{\n\t"
        ".reg .pred P1;\n\t"
        "WAIT_%=:\n\t"
        "mbarrier.try_wait.parity.acquire.cluster.shared::cta.b64 P1, [%0], %1, 0x989680;\n\t"
        "@P1 bra.uni DONE_%=;\n\t"
        "bra.uni WAIT_%=;\n\t"
        "DONE_%=:\n\t"
        "}"
        :: "r"(addr), "r"(parity) : "memory");
}
__device__ __forceinline__ void cluster_barrier() {
    asm volatile("barrier.cluster.arrive.aligned;" ::: "memory");
    asm volatile("barrier.cluster.wait.aligned;" ::: "memory");
}

// ---------------------------------------------------------------------------
// Fast activations (fp32, ~1e-6 rel error)
// ---------------------------------------------------------------------------
__device__ __forceinline__ float fast_sigmoid(float x) {
    return 1.f / (1.f + __expf(-x));
}

// ---------------------------------------------------------------------------
// Kernel 1: fold projection into layer-0 input weight (tf32-rounded output).
// ---------------------------------------------------------------------------
__global__ void combine_kernel(const float* __restrict__ proj_w,
                               const float* __restrict__ w_ih0) {
    __shared__ float sPW[32][32];
    __shared__ float sWI[32][33];
    int tx = threadIdx.x, ty = threadIdx.y;
    int d0 = blockIdx.x * 32, g0 = blockIdx.y * 32;
    float acc = 0.f;
    for (int p0 = 0; p0 < DP; p0 += 32) {
        sPW[ty][tx] = proj_w[(size_t)(p0 + ty) * DIN + d0 + tx];
        sWI[ty][tx] = w_ih0[(size_t)(g0 + ty) * DP + p0 + tx];
        __syncthreads();
#pragma unroll
        for (int p = 0; p < 32; p++) acc += sPW[p][tx] * sWI[ty][p];
        __syncthreads();
    }
    g_wc[(size_t)(d0 + tx) * G4 + g0 + ty] = to_tf32(acc);
}

__global__ void bias0_kernel(const float* __restrict__ proj_b,
                             const float* __restrict__ w_ih0,
                             const float* __restrict__ b_ih0,
                             const float* __restrict__ b_hh0) {
    int gidx = threadIdx.x;
    float acc = b_ih0[gidx] + b_hh0[gidx];
    const float* wr = w_ih0 + (size_t)gidx * DP;
    for (int p = 0; p < DP; p++) acc += proj_b[p] * wr[p];
    g_bias0[gidx] = acc;
}

// ---------------------------------------------------------------------------
// Kernel 2: layer-0 preactivations via tf32 tensor cores.
// BM=128 t, BN=64 g, K=640 in 10 chunks of 64. 8 warps (4m x 2n), each warp
// 32t x 32g via 2x4 m16n8k8 tiles. A = implicit window (contiguous slice,
// tf32-rounded at sIn staging); B = g_wc (pre-rounded). Epilogue transposes
// through SMEM to the [b][g][t] layout with float4 stores.
// ---------------------------------------------------------------------------
#define APAD0 68    // %32==4 -> A-frag rows hit distinct banks
#define BPAD0 72    // %32==8 -> B-frag k-rows hit distinct banks
__global__ void __launch_bounds__(256)
xpre0_kernel(const float* __restrict__ in) {
    __shared__ __align__(16) float sIn[128 * 32 + DIN];
    __shared__ __align__(16) float buf[128 * APAD0 + 64 * BPAD0];
    float* sAp = buf;                     // [128][APAD0]
    float* sWp = buf + 128 * APAD0;       // [64][BPAD0]
    float* sT  = buf;                     // epilogue alias [64][132]

    int tid  = threadIdx.x;
    int wid  = tid >> 5, lane = tid & 31;
    int gid  = lane >> 2, tig = lane & 3;
    int wm   = wid >> 1, wn = wid & 1;
    int t0 = blockIdx.x * 128;
    int n0 = blockIdx.y * 64;
    int b  = blockIdx.z;

    const float* inb = in + (size_t)b * SEQ * CIN;
    int base = t0 * CIN;
    for (int i = tid; i < 128 * 32 + DIN; i += 256) {
        int gi = base + i;
        sIn[i] = (gi < SEQ * CIN) ? to_tf32(inb[gi]) : 0.f;
    }

    float acc[2][4][4];
#pragma unroll
    for (int mi = 0; mi < 2; mi++)
#pragma unroll
        for (int ni = 0; ni < 4; ni++)
#pragma unroll
            for (int e = 0; e < 4; e++) acc[mi][ni][e] = 0.f;

    __syncthreads();   // sIn ready

    for (int kc = 0; kc < 10; kc++) {
        // stage A chunk: sAp[t][kk] = sIn[t*32 + kc*64 + kk]
#pragma unroll
        for (int r = 0; r < 8; r++) {
            int j = tid + r * 256;          // 2048 float4
            int t = j >> 4, k4 = (j & 15) << 2;
            *(float4*)&sAp[t * APAD0 + k4] = *(const float4*)&sIn[t * 32 + kc * 64 + k4];
        }
        // stage B chunk: sWp[k][g] from g_wc
#pragma unroll
        for (int r = 0; r < 4; r++) {
            int j = tid + r * 256;          // 1024 float4
            int k = j >> 4, g4 = (j & 15) << 2;
            *(float4*)&sWp[k * BPAD0 + g4] =
                *(const float4*)&g_wc[(size_t)(kc * 64 + k) * G4 + n0 + g4];
        }
        __syncthreads();

#pragma unroll
        for (int ki = 0; ki < 8; ki++) {
            unsigned afr[2][4];
#pragma unroll
            for (int mi = 0; mi < 2; mi++) {
                const float* ar = sAp + (wm * 32 + mi * 16 + gid) * APAD0 + ki * 8 + tig;
                afr[mi][0] = __float_as_uint(ar[0]);
                afr[mi][1] = __float_as_uint(ar[8 * APAD0]);
                afr[mi][2] = __float_as_uint(ar[4]);
                afr[mi][3] = __float_as_uint(ar[8 * APAD0 + 4]);
            }
            unsigned bfr[4][2];
#pragma unroll
            for (int ni = 0; ni < 4; ni++) {
                const float* br = sWp + (ki * 8 + tig) * BPAD0 + wn * 32 + ni * 8 + gid;
                bfr[ni][0] = __float_as_uint(br[0]);
                bfr[ni][1] = __float_as_uint(br[4 * BPAD0]);
            }
#pragma unroll
            for (int mi = 0; mi < 2; mi++)
#pragma unroll
                for (int ni = 0; ni < 4; ni++)
                    mma_tf32(acc[mi][ni], afr[mi], bfr[ni]);
        }
        __syncthreads();
    }

    // epilogue: transpose to sT[g][t] (pad 132: t-rows), then coalesced stores
#pragma unroll
    for (int mi = 0; mi < 2; mi++)
#pragma unroll
        for (int ni = 0; ni < 4; ni++) {
            int tl = wm * 32 + mi * 16 + gid;
            int gl = wn * 32 + ni * 8 + tig * 2;
            sT[gl * 132 + tl]           = acc[mi][ni][0];
            sT[(gl + 1) * 132 + tl]     = acc[mi][ni][1];
            sT[gl * 132 + tl + 8]       = acc[mi][ni][2];
            sT[(gl + 1) * 132 + tl + 8] = acc[mi][ni][3];
        }
    __syncthreads();
#pragma unroll
    for (int r = 0; r < 8; r++) {
        int j = tid + r * 256;              // 2048 float4
        int g = j >> 5, t4 = (j & 31) << 2;
        if (t0 + t4 + 4 <= XT) {
            float4 v = *(float4*)&sT[g * 132 + t4];
            float bv = g_bias0[n0 + g];
            v.x += bv; v.y += bv; v.z += bv; v.w += bv;
            *(float4*)&g_xpre[((size_t)b * G4 + n0 + g) * XT + t0 + t4] = v;
        }
    }
}

// ---------------------------------------------------------------------------
// Kernel 3: input preactivations for layers 1..3 via tf32 tensor cores.
// BM=64 t, BN=64 g, K=128 (single chunk). 8 warps (2m x 4n), each warp
// 32t x 16g via 2x2 m16n8k8 tiles.
// ---------------------------------------------------------------------------
#define APAD1 132   // %32==4
#define BPAD1 72    // %32==8
__global__ void __launch_bounds__(256)
gemm_ih_kernel(const float* __restrict__ w_ih,
               const float* __restrict__ b_ih,
               const float* __restrict__ b_hh) {
    __shared__ __align__(16) float buf[64 * APAD1 + 128 * BPAD1];
    float* sA = buf;                      // [64][APAD1]
    float* sB = buf + 64 * APAD1;         // [128][BPAD1]
    float* sT = buf;                      // epilogue alias [64][68]

    int tid  = threadIdx.x;
    int wid  = tid >> 5, lane = tid & 31;
    int gid  = lane >> 2, tig = lane & 3;
    int wm   = wid & 1, wn = wid >> 1;
    int t0 = blockIdx.x * 64;
    int n0 = blockIdx.y * 64;
    int b  = blockIdx.z;

    // stage A: sA[t][k] = tf32(hseq[b][t0+t][k])
#pragma unroll
    for (int r = 0; r < 8; r++) {
        int j = tid + r * 256;              // 2048 float4
        int t = j >> 5, k4 = (j & 31) << 2;
        float4 v = make_float4(0.f, 0.f, 0.f, 0.f);
        if (t0 + t < L_OUT)
            v = *(const float4*)&g_hseq[((size_t)b * L_OUT + t0 + t) * HID + k4];
        v.x = to_tf32(v.x); v.y = to_tf32(v.y); v.z = to_tf32(v.z); v.w = to_tf32(v.w);
        *(float4*)&sA[t * APAD1 + k4] = v;
    }
    // stage B transposed: sB[k][g] = tf32(w_ih[n0+g][k]); g fastest across lanes
#pragma unroll
    for (int r = 0; r < 8; r++) {
        int j = tid + r * 256;              // 2048 groups (g, k4)
        int g = j & 63, kg = j >> 6;
        int k4 = kg << 2;
        float4 v = *(const float4*)&w_ih[(size_t)(n0 + g) * HID + k4];
        sB[(k4 + 0) * BPAD1 + g] = to_tf32(v.x);
        sB[(k4 + 1) * BPAD1 + g] = to_tf32(v.y);
        sB[(k4 + 2) * BPAD1 + g] = to_tf32(v.z);
        sB[(k4 + 3) * BPAD1 + g] = to_tf32(v.w);
    }
    __syncthreads();

    float acc[2][2][4];
#pragma unroll
    for (int mi = 0; mi < 2; mi++)
#pragma unroll
        for (int ni = 0; ni < 2; ni++)
#pragma unroll
            for (int e = 0; e < 4; e++) acc[mi][ni][e] = 0.f;

#pragma unroll
    for (int ki = 0; ki < 16; ki++) {
        unsigned afr[2][4];
#pragma unroll
        for (int mi = 0; mi < 2; mi++) {
            const float* ar = sA + (wm * 32 + mi * 16 + gid) * APAD1 + ki * 8 + tig;
            afr[mi][0] = __float_as_uint(ar[0]);
            afr[mi][1] = __float_as_uint(ar[8 * APAD1]);
            afr[mi][2] = __float_as_uint(ar[4]);
            afr[mi][3] = __float_as_uint(ar[8 * APAD1 + 4]);
        }
        unsigned bfr[2][2];
#pragma unroll
        for (int ni = 0; ni < 2; ni++) {
            const float* br = sB + (ki * 8 + tig) * BPAD1 + wn * 16 + ni * 8 + gid;
            bfr[ni][0] = __float_as_uint(br[0]);
            bfr[ni][1] = __float_as_uint(br[4 * BPAD1]);
        }
#pragma unroll
        for (int mi = 0; mi < 2; mi++)
#pragma unroll
            for (int ni = 0; ni < 2; ni++)
                mma_tf32(acc[mi][ni], afr[mi], bfr[ni]);
    }
    __syncthreads();

    // epilogue: transpose to sT[g][t] (pad 68), then coalesced stores + bias
#pragma unroll
    for (int mi = 0; mi < 2; mi++)
#pragma unroll
        for (int ni = 0; ni < 2; ni++) {
            int tl = wm * 32 + mi * 16 + gid;
            int gl = wn * 16 + ni * 8 + tig * 2;
            sT[gl * 68 + tl]           = acc[mi][ni][0];
            sT[(gl + 1) * 68 + tl]     = acc[mi][ni][1];
            sT[gl * 68 + tl + 8]       = acc[mi][ni][2];
            sT[(gl + 1) * 68 + tl + 8] = acc[mi][ni][3];
        }
    __syncthreads();
#pragma unroll
    for (int r = 0; r < 4; r++) {
        int j = tid + r * 256;              // 1024 float4
        int g = j >> 4, t4 = (j & 15) << 2;
        if (t0 + t4 + 4 <= XT) {
            float4 v = *(float4*)&sT[g * 68 + t4];
            float bv = b_ih[n0 + g] + b_hh[n0 + g];
            v.x += bv; v.y += bv; v.z += bv; v.w += bv;
            *(float4*)&g_xpre[((size_t)b * G4 + n0 + g) * XT + t0 + t4] = v;
        }
    }
}

// ---------------------------------------------------------------------------
// Kernel 4: recurrent scan — R10 (unchanged; measured best).
// ---------------------------------------------------------------------------
__global__ void __cluster_dims__(2, 1, 1) __launch_bounds__(256, 1)
scan_kernel(const float* __restrict__ w_hh) {
    __shared__ __align__(16) float hbuf[2][64];
    __shared__ __align__(16) float land[2][64];
    __shared__ __align__(8) unsigned long long mbars[2];

    int tid  = threadIdx.x;
    int rank = blockIdx.x & 1;
    int b    = blockIdx.x >> 1;
    int gate = tid & 3;
    int ul   = tid >> 2;
    int ug   = rank * 64 + ul;
    int row  = gate * HID + ug;
    int kown  = rank * 64;
    int kpeer = (rank ^ 1) * 64;

    unsigned long long wown[32], wpeer[32];
    {
        const ulonglong2* wr = (const ulonglong2*)(w_hh + (size_t)row * HID + kown);
#pragma unroll
        for (int k = 0; k < 16; k++) {
            ulonglong2 u = wr[k];
            wown[2 * k]     = u.x;
            wown[2 * k + 1] = u.y;
        }
        const ulonglong2* wp = (const ulonglong2*)(w_hh + (size_t)row * HID + kpeer);
#pragma unroll
        for (int k = 0; k < 16; k++) {
            ulonglong2 u = wp[k];
            wpeer[2 * k]     = u.x;
            wpeer[2 * k + 1] = u.y;
        }
    }

    if (tid < 64) {
        hbuf[0][tid] = 0.f; hbuf[1][tid] = 0.f;
        land[0][tid] = 0.f; land[1][tid] = 0.f;
    }
    unsigned bar0 = smem_u32(&mbars[0]);
    unsigned bar1 = smem_u32(&mbars[1]);
    if (tid == 0) { mbar_init(bar0, 1); mbar_init(bar1, 1); }
    __syncthreads();
    cluster_barrier();

    unsigned peer = rank ^ 1;
    unsigned peer_l0 = mapa_rank(smem_u32(&land[0][0]), peer) + (unsigned)ul * 4u;
    unsigned peer_l1 = mapa_rank(smem_u32(&land[1][0]), peer) + (unsigned)ul * 4u;
    unsigned peer_b0 = mapa_rank(bar0, peer);
    unsigned peer_b1 = mapa_rank(bar1, peer);

    float c = 0.f;
    const size_t hrow = (size_t)b * L_OUT;
    const float* xrow_p = g_xpre + ((size_t)b * G4 + row) * XT;

    const float s_ = (gate == 2) ? 2.f : 1.f;
    const float m_ = (gate == 2) ? 2.f : 1.f;
    const float a_ = (gate == 2) ? -1.f : 0.f;
    const bool  tail = (gate == 0);

    float4 xcur = *(const float4*)(xrow_p);

    for (int t4 = 0; t4 < L_OUT; t4 += 4) {
        float4 xnxt = *(const float4*)(xrow_p + t4 + 4);

#pragma unroll
        for (int s = 0; s < 4; s++) {
            int t = t4 + s;
            float xp = (s == 0) ? xcur.x : (s == 1) ? xcur.y : (s == 2) ? xcur.z : xcur.w;

            if (tid == 0 && t + 1 < L_OUT)
                mbar_expect_tx((t & 1) ? bar1 : bar0, 256);

            unsigned long long a0 = pk2(0.f, 0.f), a1 = pk2(0.f, 0.f);
            unsigned long long a2 = pk2(0.f, 0.f), a3 = pk2(0.f, 0.f);

            {
                const ulonglong2* h2 = (const ulonglong2*)hbuf[(t + 1) & 1];
#pragma unroll
                for (int k = 0; k < 8; k++) {
                    ulonglong2 u = h2[2 * k];
                    ulonglong2 v = h2[2 * k + 1];
                    fma2(a0, wown[4 * k],     u.x);
                    fma2(a1, wown[4 * k + 1], u.y);
                    fma2(a2, wown[4 * k + 2], v.x);
                    fma2(a3, wown[4 * k + 3], v.y);
                }
            }

            if (t > 0) {
                int pv = t - 1;
                mbar_wait_cluster((pv & 1) ? bar1 : bar0, (unsigned)((pv >> 1) & 1));
            }

            {
                const ulonglong2* h2 = (const ulonglong2*)land[(t + 1) & 1];
#pragma unroll
                for (int k = 0; k < 8; k++) {
                    ulonglong2 u = h2[2 * k];
                    ulonglong2 v = h2[2 * k + 1];
                    fma2(a0, wpeer[4 * k],     u.x);
                    fma2(a1, wpeer[4 * k + 1], u.y);
                    fma2(a2, wpeer[4 * k + 2], v.x);
                    fma2(a3, wpeer[4 * k + 3], v.y);
                }
            }

            float2 q0 = unpk2(a0), q1 = unpk2(a1), q2 = unpk2(a2), q3 = unpk2(a3);
            float pre = (((q0.x + q0.y) + (q1.x + q1.y)) +
                         ((q2.x + q2.y) + (q3.x + q3.y))) + xp;
            float act = fmaf(m_, fast_sigmoid(s_ * pre), a_);

            float fv = __shfl_down_sync(0xffffffffu, act, 1);
            float gv = __shfl_down_sync(0xffffffffu, act, 2);
            float ov = __shfl_down_sync(0xffffffffu, act, 3);

            if (tail) {
                c = fv * c + act * gv;
                float tc = fmaf(2.f, fast_sigmoid(2.f * c), -1.f);
                float h  = ov * tc;
                if (t + 1 < L_OUT)
                    st_async_f32((t & 1) ? peer_l1 : peer_l0, h,
                                 (t & 1) ? peer_b1 : peer_b0);
                hbuf[t & 1][ul] = h;
                g_hseq[(hrow + t) * HID + ug] = h;
            }
            __syncthreads();
        }
        xcur = xnxt;
    }
    cluster_barrier();
}

// ---------------------------------------------------------------------------
// Kernel 5: readout.
// ---------------------------------------------------------------------------
__global__ void out_kernel(const float* __restrict__ out_w,
                           const float* __restrict__ out_b,
                           float* __restrict__ out) {
    __shared__ float h[HID];
    int b = blockIdx.x;
    if (threadIdx.x < HID)
        h[threadIdx.x] = g_hseq[((size_t)b * L_OUT + (L_OUT - 1)) * HID + threadIdx.x];
    __syncthreads();
    if (threadIdx.x < LBL) {
        float acc = out_b[threadIdx.x];
        const float* wr = out_w + (size_t)threadIdx.x * HID;
#pragma unroll 8
        for (int k = 0; k < HID; k++) acc += wr[k] * h[k];
        out[(size_t)b * LBL + threadIdx.x] = acc;
    }
}

// ---------------------------------------------------------------------------
// Launch
// ---------------------------------------------------------------------------
extern "C" void kernel_launch(void* const* d_in, const int* in_sizes, int n_in,
                              void* d_out, int out_size) {
    const float* inputs    = (const float*)d_in[0];
    const float* proj_w    = (const float*)d_in[4];
    const float* proj_b    = (const float*)d_in[5];
    const float* w_ih0     = (const float*)d_in[6];
    const float* w_hh0     = (const float*)d_in[7];
    const float* b_ih0     = (const float*)d_in[8];
    const float* b_hh0     = (const float*)d_in[9];
    const float* w_ih_rest = (const float*)d_in[10];
    const float* w_hh_rest = (const float*)d_in[11];
    const float* b_ih_rest = (const float*)d_in[12];
    const float* b_hh_rest = (const float*)d_in[13];
    const float* out_w     = (const float*)d_in[14];
    const float* out_b     = (const float*)d_in[15];
    float* out = (float*)d_out;

    combine_kernel<<<dim3(DIN / 32, G4 / 32), dim3(32, 32)>>>(proj_w, w_ih0);
    bias0_kernel<<<1, G4>>>(proj_b, w_ih0, b_ih0, b_hh0);

    xpre0_kernel<<<dim3((L_OUT + 127) / 128, G4 / 64, BATCH), 256>>>(inputs);

    scan_kernel<<<BATCH * 2, 256>>>(w_hh0);

    for (int l = 0; l < 3; l++) {
        gemm_ih_kernel<<<dim3((L_OUT + 63) / 64, G4 / 64, BATCH), 256>>>(
            w_ih_rest + (size_t)l * G4 * HID,
            b_ih_rest + (size_t)l * G4,
            b_hh_rest + (size_t)l * G4);
        scan_kernel<<<BATCH * 2, 256>>>(w_hh_rest + (size_t)l * G4 * HID);
    }

    out_kernel<<<BATCH, 128>>>(out_w, out_b, out);
}

// round 12
// speedup vs baseline: 2.7426x; 1.1493x over previous
#include <cuda_runtime.h>
#include <cuda_bf16.h>
#include <cstdint>

// ---------------------------------------------------------------------------
// Problem constants
// ---------------------------------------------------------------------------
#define BATCH   64
#define SEQ     2048
#define CIN     32
#define WIN     20
#define DIN     (WIN * CIN)      // 640
#define DP      (DIN / 2)        // 320
#define HID     128
#define G4      (4 * HID)        // 512
#define L_OUT   (SEQ - WIN)      // 2028
#define XT      2032             // padded time stride for g_xpre
#define LBL     48

// ---------------------------------------------------------------------------
// Scratch (static __device__ arrays; no cudaMalloc allowed)
// ---------------------------------------------------------------------------
__device__ float g_wc[DIN * G4];                       // combined proj->ih0 weight [k][g], tf32-rounded
__device__ float g_bias0[G4];
__device__ float g_xpre[(size_t)BATCH * G4 * XT];      // preactivations, [b][g][t] (t-major)
__device__ float g_hseq[(size_t)BATCH * L_OUT * HID];  // per-step hidden outputs [b][t][h]

// ---------------------------------------------------------------------------
// Packed fp32x2 helpers (scan only)
// ---------------------------------------------------------------------------
__device__ __forceinline__ unsigned long long pk2(float x, float y) {
    unsigned long long r;
    asm("mov.b64 %0, {%1, %2};" : "=l"(r) : "f"(x), "f"(y));
    return r;
}
__device__ __forceinline__ float2 unpk2(unsigned long long v) {
    float2 r;
    asm("mov.b64 {%0, %1}, %2;" : "=f"(r.x), "=f"(r.y) : "l"(v));
    return r;
}
__device__ __forceinline__ void fma2(unsigned long long& d, unsigned long long a,
                                     unsigned long long b) {
    asm("fma.rn.f32x2 %0, %1, %2, %3;" : "=l"(d) : "l"(a), "l"(b), "l"(d));
}

// ---------------------------------------------------------------------------
// tf32 helpers
// ---------------------------------------------------------------------------
__device__ __forceinline__ float to_tf32(float x) {
    unsigned u;
    asm("cvt.rna.tf32.f32 %0, %1;" : "=r"(u) : "f"(x));
    return __uint_as_float(u);
}
// D(16x8,f32) += A(16x8 tf32, row) * B(8x8 tf32, col)
__device__ __forceinline__ void mma_tf32(float* d, const unsigned* a, const unsigned* b) {
    asm volatile(
        "mma.sync.aligned.m16n8k8.row.col.f32.tf32.tf32.f32 "
        "{%0,%1,%2,%3}, {%4,%5,%6,%7}, {%8,%9}, {%0,%1,%2,%3};"
        : "+f"(d[0]), "+f"(d[1]), "+f"(d[2]), "+f"(d[3])
        : "r"(a[0]), "r"(a[1]), "r"(a[2]), "r"(a[3]), "r"(b[0]), "r"(b[1]));
}

// ---------------------------------------------------------------------------
// Cluster / mbarrier helpers
// ---------------------------------------------------------------------------
__device__ __forceinline__ unsigned smem_u32(const void* p) {
    return (unsigned)__cvta_generic_to_shared(p);
}
__device__ __forceinline__ unsigned mapa_rank(unsigned addr, unsigned rank) {
    unsigned r;
    asm("mapa.shared::cluster.u32 %0, %1, %2;" : "=r"(r) : "r"(addr), "r"(rank));
    return r;
}
__device__ __forceinline__ void mbar_init(unsigned addr, unsigned cnt) {
    asm volatile("mbarrier.init.shared.b64 [%0], %1;" :: "r"(addr), "r"(cnt) : "memory");
}
__device__ __forceinline__ void mbar_expect_tx(unsigned addr, unsigned bytes) {
    asm volatile("mbarrier.arrive.expect_tx.shared.b64 _, [%0], %1;"
                 :: "r"(addr), "r"(bytes) : "memory");
}
// Packed remote SMEM store (8 bytes) with mbarrier tx-completion.
__device__ __forceinline__ void st_async_f32x2(unsigned raddr, float x, float y,
                                               unsigned rmbar) {
    unsigned long long v = pk2(x, y);   // little-endian: x at raddr, y at raddr+4
    asm volatile(
        "st.async.shared::cluster.mbarrier::complete_tx::bytes.b64 [%0], %1, [%2];"
        :: "r"(raddr), "l"(v), "r"(rmbar) : "memory");
}
__device__ __forceinline__ void mbar_wait_cluster(unsigned addr, unsigned parity) {
    asm volatile(
        "{\n\t"
        ".reg .pred P1;\n\t"
        "WAIT_%=:\n\t"
        "mbarrier.try_wait.parity.acquire.cluster.shared::cta.b64 P1, [%0], %1, 0x989680;\n\t"
        "@P1 bra.uni DONE_%=;\n\t"
        "bra.uni WAIT_%=;\n\t"
        "DONE_%=:\n\t"
        "}"
        :: "r"(addr), "r"(parity) : "memory");
}
__device__ __forceinline__ void cluster_barrier() {
    asm volatile("barrier.cluster.arrive.aligned;" ::: "memory");
    asm volatile("barrier.cluster.wait.aligned;" ::: "memory");
}

// ---------------------------------------------------------------------------
// Fast activations: HW tanh unit (sm_75+), sigmoid via tanh identity.
// ---------------------------------------------------------------------------
__device__ __forceinline__ float tanhf_fast(float x) {
    float y;
    asm("tanh.approx.f32 %0, %1;" : "=f"(y) : "f"(x));
    return y;
}

// ---------------------------------------------------------------------------
// Kernel 1: fold projection into layer-0 input weight (tf32-rounded output).
// ---------------------------------------------------------------------------
__global__ void combine_kernel(const float* __restrict__ proj_w,
                               const float* __restrict__ w_ih0) {
    __shared__ float sPW[32][32];
    __shared__ float sWI[32][33];
    int tx = threadIdx.x, ty = threadIdx.y;
    int d0 = blockIdx.x * 32, g0 = blockIdx.y * 32;
    float acc = 0.f;
    for (int p0 = 0; p0 < DP; p0 += 32) {
        sPW[ty][tx] = proj_w[(size_t)(p0 + ty) * DIN + d0 + tx];
        sWI[ty][tx] = w_ih0[(size_t)(g0 + ty) * DP + p0 + tx];
        __syncthreads();
#pragma unroll
        for (int p = 0; p < 32; p++) acc += sPW[p][tx] * sWI[ty][p];
        __syncthreads();
    }
    g_wc[(size_t)(d0 + tx) * G4 + g0 + ty] = to_tf32(acc);
}

__global__ void bias0_kernel(const float* __restrict__ proj_b,
                             const float* __restrict__ w_ih0,
                             const float* __restrict__ b_ih0,
                             const float* __restrict__ b_hh0) {
    int gidx = threadIdx.x;
    float acc = b_ih0[gidx] + b_hh0[gidx];
    const float* wr = w_ih0 + (size_t)gidx * DP;
    for (int p = 0; p < DP; p++) acc += proj_b[p] * wr[p];
    g_bias0[gidx] = acc;
}

// ---------------------------------------------------------------------------
// Kernel 2: layer-0 preactivations via tf32 tensor cores (R11, unchanged).
// ---------------------------------------------------------------------------
#define APAD0 68
#define BPAD0 72
__global__ void __launch_bounds__(256)
xpre0_kernel(const float* __restrict__ in) {
    __shared__ __align__(16) float sIn[128 * 32 + DIN];
    __shared__ __align__(16) float buf[128 * APAD0 + 64 * BPAD0];
    float* sAp = buf;
    float* sWp = buf + 128 * APAD0;
    float* sT  = buf;

    int tid  = threadIdx.x;
    int wid  = tid >> 5, lane = tid & 31;
    int gid  = lane >> 2, tig = lane & 3;
    int wm   = wid >> 1, wn = wid & 1;
    int t0 = blockIdx.x * 128;
    int n0 = blockIdx.y * 64;
    int b  = blockIdx.z;

    const float* inb = in + (size_t)b * SEQ * CIN;
    int base = t0 * CIN;
    for (int i = tid; i < 128 * 32 + DIN; i += 256) {
        int gi = base + i;
        sIn[i] = (gi < SEQ * CIN) ? to_tf32(inb[gi]) : 0.f;
    }

    float acc[2][4][4];
#pragma unroll
    for (int mi = 0; mi < 2; mi++)
#pragma unroll
        for (int ni = 0; ni < 4; ni++)
#pragma unroll
            for (int e = 0; e < 4; e++) acc[mi][ni][e] = 0.f;

    __syncthreads();

    for (int kc = 0; kc < 10; kc++) {
#pragma unroll
        for (int r = 0; r < 8; r++) {
            int j = tid + r * 256;
            int t = j >> 4, k4 = (j & 15) << 2;
            *(float4*)&sAp[t * APAD0 + k4] = *(const float4*)&sIn[t * 32 + kc * 64 + k4];
        }
#pragma unroll
        for (int r = 0; r < 4; r++) {
            int j = tid + r * 256;
            int k = j >> 4, g4 = (j & 15) << 2;
            *(float4*)&sWp[k * BPAD0 + g4] =
                *(const float4*)&g_wc[(size_t)(kc * 64 + k) * G4 + n0 + g4];
        }
        __syncthreads();

#pragma unroll
        for (int ki = 0; ki < 8; ki++) {
            unsigned afr[2][4];
#pragma unroll
            for (int mi = 0; mi < 2; mi++) {
                const float* ar = sAp + (wm * 32 + mi * 16 + gid) * APAD0 + ki * 8 + tig;
                afr[mi][0] = __float_as_uint(ar[0]);
                afr[mi][1] = __float_as_uint(ar[8 * APAD0]);
                afr[mi][2] = __float_as_uint(ar[4]);
                afr[mi][3] = __float_as_uint(ar[8 * APAD0 + 4]);
            }
            unsigned bfr[4][2];
#pragma unroll
            for (int ni = 0; ni < 4; ni++) {
                const float* br = sWp + (ki * 8 + tig) * BPAD0 + wn * 32 + ni * 8 + gid;
                bfr[ni][0] = __float_as_uint(br[0]);
                bfr[ni][1] = __float_as_uint(br[4 * BPAD0]);
            }
#pragma unroll
            for (int mi = 0; mi < 2; mi++)
#pragma unroll
                for (int ni = 0; ni < 4; ni++)
                    mma_tf32(acc[mi][ni], afr[mi], bfr[ni]);
        }
        __syncthreads();
    }

#pragma unroll
    for (int mi = 0; mi < 2; mi++)
#pragma unroll
        for (int ni = 0; ni < 4; ni++) {
            int tl = wm * 32 + mi * 16 + gid;
            int gl = wn * 32 + ni * 8 + tig * 2;
            sT[gl * 132 + tl]           = acc[mi][ni][0];
            sT[(gl + 1) * 132 + tl]     = acc[mi][ni][1];
            sT[gl * 132 + tl + 8]       = acc[mi][ni][2];
            sT[(gl + 1) * 132 + tl + 8] = acc[mi][ni][3];
        }
    __syncthreads();
#pragma unroll
    for (int r = 0; r < 8; r++) {
        int j = tid + r * 256;
        int g = j >> 5, t4 = (j & 31) << 2;
        if (t0 + t4 + 4 <= XT) {
            float4 v = *(float4*)&sT[g * 132 + t4];
            float bv = g_bias0[n0 + g];
            v.x += bv; v.y += bv; v.z += bv; v.w += bv;
            *(float4*)&g_xpre[((size_t)b * G4 + n0 + g) * XT + t0 + t4] = v;
        }
    }
}

// ---------------------------------------------------------------------------
// Kernel 3: input preactivations for layers 1..3 via tf32 (R11, unchanged).
// ---------------------------------------------------------------------------
#define APAD1 132
#define BPAD1 72
__global__ void __launch_bounds__(256)
gemm_ih_kernel(const float* __restrict__ w_ih,
               const float* __restrict__ b_ih,
               const float* __restrict__ b_hh) {
    __shared__ __align__(16) float buf[64 * APAD1 + 128 * BPAD1];
    float* sA = buf;
    float* sB = buf + 64 * APAD1;
    float* sT = buf;

    int tid  = threadIdx.x;
    int wid  = tid >> 5, lane = tid & 31;
    int gid  = lane >> 2, tig = lane & 3;
    int wm   = wid & 1, wn = wid >> 1;
    int t0 = blockIdx.x * 64;
    int n0 = blockIdx.y * 64;
    int b  = blockIdx.z;

#pragma unroll
    for (int r = 0; r < 8; r++) {
        int j = tid + r * 256;
        int t = j >> 5, k4 = (j & 31) << 2;
        float4 v = make_float4(0.f, 0.f, 0.f, 0.f);
        if (t0 + t < L_OUT)
            v = *(const float4*)&g_hseq[((size_t)b * L_OUT + t0 + t) * HID + k4];
        v.x = to_tf32(v.x); v.y = to_tf32(v.y); v.z = to_tf32(v.z); v.w = to_tf32(v.w);
        *(float4*)&sA[t * APAD1 + k4] = v;
    }
#pragma unroll
    for (int r = 0; r < 8; r++) {
        int j = tid + r * 256;
        int g = j & 63, kg = j >> 6;
        int k4 = kg << 2;
        float4 v = *(const float4*)&w_ih[(size_t)(n0 + g) * HID + k4];
        sB[(k4 + 0) * BPAD1 + g] = to_tf32(v.x);
        sB[(k4 + 1) * BPAD1 + g] = to_tf32(v.y);
        sB[(k4 + 2) * BPAD1 + g] = to_tf32(v.z);
        sB[(k4 + 3) * BPAD1 + g] = to_tf32(v.w);
    }
    __syncthreads();

    float acc[2][2][4];
#pragma unroll
    for (int mi = 0; mi < 2; mi++)
#pragma unroll
        for (int ni = 0; ni < 2; ni++)
#pragma unroll
            for (int e = 0; e < 4; e++) acc[mi][ni][e] = 0.f;

#pragma unroll
    for (int ki = 0; ki < 16; ki++) {
        unsigned afr[2][4];
#pragma unroll
        for (int mi = 0; mi < 2; mi++) {
            const float* ar = sA + (wm * 32 + mi * 16 + gid) * APAD1 + ki * 8 + tig;
            afr[mi][0] = __float_as_uint(ar[0]);
            afr[mi][1] = __float_as_uint(ar[8 * APAD1]);
            afr[mi][2] = __float_as_uint(ar[4]);
            afr[mi][3] = __float_as_uint(ar[8 * APAD1 + 4]);
        }
        unsigned bfr[2][2];
#pragma unroll
        for (int ni = 0; ni < 2; ni++) {
            const float* br = sB + (ki * 8 + tig) * BPAD1 + wn * 16 + ni * 8 + gid;
            bfr[ni][0] = __float_as_uint(br[0]);
            bfr[ni][1] = __float_as_uint(br[4 * BPAD1]);
        }
#pragma unroll
        for (int mi = 0; mi < 2; mi++)
#pragma unroll
            for (int ni = 0; ni < 2; ni++)
                mma_tf32(acc[mi][ni], afr[mi], bfr[ni]);
    }
    __syncthreads();

#pragma unroll
    for (int mi = 0; mi < 2; mi++)
#pragma unroll
        for (int ni = 0; ni < 2; ni++) {
            int tl = wm * 32 + mi * 16 + gid;
            int gl = wn * 16 + ni * 8 + tig * 2;
            sT[gl * 68 + tl]           = acc[mi][ni][0];
            sT[(gl + 1) * 68 + tl]     = acc[mi][ni][1];
            sT[gl * 68 + tl + 8]       = acc[mi][ni][2];
            sT[(gl + 1) * 68 + tl + 8] = acc[mi][ni][3];
        }
    __syncthreads();
#pragma unroll
    for (int r = 0; r < 4; r++) {
        int j = tid + r * 256;
        int g = j >> 4, t4 = (j & 15) << 2;
        if (t0 + t4 + 4 <= XT) {
            float4 v = *(float4*)&sT[g * 68 + t4];
            float bv = b_ih[n0 + g] + b_hh[n0 + g];
            v.x += bv; v.y += bv; v.z += bv; v.w += bv;
            *(float4*)&g_xpre[((size_t)b * G4 + n0 + g) * XT + t0 + t4] = v;
        }
    }
}

// ---------------------------------------------------------------------------
// Kernel 4: recurrent scan — R10 structure with two serial-path cuts:
//  (1) tanh.approx.f32 HW unit for all activations: sigmoid(x) =
//      0.5*tanh(0.5x)+0.5, tanh direct. Replaces EX2+RCP chains (~45 cyc)
//      with one MUFU-class op (~16) twice on the critical path.
//  (2) packed .b64 st.asyncs: adjacent units' tails are 4 lanes apart in
//      the same warp, so shfl_down(h,4) lets even-unit tails send 2 h
//      values per store — 32 remote tx-updates/step instead of 64, halving
//      the serialized mbarrier-completion chain that gates the peer's wait.
// Protocol/parity identical to R10 (proven); expect_tx stays 256 bytes.
// ---------------------------------------------------------------------------
__global__ void __cluster_dims__(2, 1, 1) __launch_bounds__(256, 1)
scan_kernel(const float* __restrict__ w_hh) {
    __shared__ __align__(16) float hbuf[2][64];
    __shared__ __align__(16) float land[2][64];
    __shared__ __align__(8) unsigned long long mbars[2];

    int tid  = threadIdx.x;
    int rank = blockIdx.x & 1;
    int b    = blockIdx.x >> 1;
    int gate = tid & 3;
    int ul   = tid >> 2;
    int ug   = rank * 64 + ul;
    int row  = gate * HID + ug;
    int kown  = rank * 64;
    int kpeer = (rank ^ 1) * 64;

    unsigned long long wown[32], wpeer[32];
    {
        const ulonglong2* wr = (const ulonglong2*)(w_hh + (size_t)row * HID + kown);
#pragma unroll
        for (int k = 0; k < 16; k++) {
            ulonglong2 u = wr[k];
            wown[2 * k]     = u.x;
            wown[2 * k + 1] = u.y;
        }
        const ulonglong2* wp = (const ulonglong2*)(w_hh + (size_t)row * HID + kpeer);
#pragma unroll
        for (int k = 0; k < 16; k++) {
            ulonglong2 u = wp[k];
            wpeer[2 * k]     = u.x;
            wpeer[2 * k + 1] = u.y;
        }
    }

    if (tid < 64) {
        hbuf[0][tid] = 0.f; hbuf[1][tid] = 0.f;
        land[0][tid] = 0.f; land[1][tid] = 0.f;
    }
    unsigned bar0 = smem_u32(&mbars[0]);
    unsigned bar1 = smem_u32(&mbars[1]);
    if (tid == 0) { mbar_init(bar0, 1); mbar_init(bar1, 1); }
    __syncthreads();
    cluster_barrier();

    unsigned peer = rank ^ 1;
    unsigned peer_l0 = mapa_rank(smem_u32(&land[0][0]), peer) + (unsigned)ul * 4u;
    unsigned peer_l1 = mapa_rank(smem_u32(&land[1][0]), peer) + (unsigned)ul * 4u;
    unsigned peer_b0 = mapa_rank(bar0, peer);
    unsigned peer_b1 = mapa_rank(bar1, peer);

    float c = 0.f;
    const size_t hrow = (size_t)b * L_OUT;
    const float* xrow_p = g_xpre + ((size_t)b * G4 + row) * XT;

    // activation via tanh unit: act = A*tanh(B*pre) + C
    const float A_ = (gate == 2) ? 1.f : 0.5f;
    const float B_ = (gate == 2) ? 1.f : 0.5f;
    const float C_ = (gate == 2) ? 0.f : 0.5f;
    const bool  tail   = (gate == 0);
    const bool  sender = tail && ((ul & 1) == 0);

    float4 xcur = *(const float4*)(xrow_p);

    for (int t4 = 0; t4 < L_OUT; t4 += 4) {
        float4 xnxt = *(const float4*)(xrow_p + t4 + 4);

#pragma unroll
        for (int s = 0; s < 4; s++) {
            int t = t4 + s;
            float xp = (s == 0) ? xcur.x : (s == 1) ? xcur.y : (s == 2) ? xcur.z : xcur.w;

            if (tid == 0 && t + 1 < L_OUT)
                mbar_expect_tx((t & 1) ? bar1 : bar0, 256);

            unsigned long long a0 = pk2(0.f, 0.f), a1 = pk2(0.f, 0.f);
            unsigned long long a2 = pk2(0.f, 0.f), a3 = pk2(0.f, 0.f);

            {
                const ulonglong2* h2 = (const ulonglong2*)hbuf[(t + 1) & 1];
#pragma unroll
                for (int k = 0; k < 8; k++) {
                    ulonglong2 u = h2[2 * k];
                    ulonglong2 v = h2[2 * k + 1];
                    fma2(a0, wown[4 * k],     u.x);
                    fma2(a1, wown[4 * k + 1], u.y);
                    fma2(a2, wown[4 * k + 2], v.x);
                    fma2(a3, wown[4 * k + 3], v.y);
                }
            }

            if (t > 0) {
                int pv = t - 1;
                mbar_wait_cluster((pv & 1) ? bar1 : bar0, (unsigned)((pv >> 1) & 1));
            }

            {
                const ulonglong2* h2 = (const ulonglong2*)land[(t + 1) & 1];
#pragma unroll
                for (int k = 0; k < 8; k++) {
                    ulonglong2 u = h2[2 * k];
                    ulonglong2 v = h2[2 * k + 1];
                    fma2(a0, wpeer[4 * k],     u.x);
                    fma2(a1, wpeer[4 * k + 1], u.y);
                    fma2(a2, wpeer[4 * k + 2], v.x);
                    fma2(a3, wpeer[4 * k + 3], v.y);
                }
            }

            float2 q0 = unpk2(a0), q1 = unpk2(a1), q2 = unpk2(a2), q3 = unpk2(a3);
            float pre = (((q0.x + q0.y) + (q1.x + q1.y)) +
                         ((q2.x + q2.y) + (q3.x + q3.y))) + xp;
            float act = fmaf(A_, tanhf_fast(B_ * pre), C_);

            float fv = __shfl_down_sync(0xffffffffu, act, 1);
            float gv = __shfl_down_sync(0xffffffffu, act, 2);
            float ov = __shfl_down_sync(0xffffffffu, act, 3);

            float h = 0.f;
            if (tail) {
                c = fmaf(fv, c, act * gv);        // act == i
                h = ov * tanhf_fast(c);
            }
            // partner unit's h (ul+1 lives 4 lanes up); all lanes execute
            float hp = __shfl_down_sync(0xffffffffu, h, 4);
            if (tail) {
                if (sender && t + 1 < L_OUT)
                    st_async_f32x2((t & 1) ? peer_l1 : peer_l0, h, hp,
                                   (t & 1) ? peer_b1 : peer_b0);
                hbuf[t & 1][ul] = h;
                g_hseq[(hrow + t) * HID + ug] = h;
            }
            __syncthreads();
        }
        xcur = xnxt;
    }
    cluster_barrier();
}

// ---------------------------------------------------------------------------
// Kernel 5: readout.
// ---------------------------------------------------------------------------
__global__ void out_kernel(const float* __restrict__ out_w,
                           const float* __restrict__ out_b,
                           float* __restrict__ out) {
    __shared__ float h[HID];
    int b = blockIdx.x;
    if (threadIdx.x < HID)
        h[threadIdx.x] = g_hseq[((size_t)b * L_OUT + (L_OUT - 1)) * HID + threadIdx.x];
    __syncthreads();
    if (threadIdx.x < LBL) {
        float acc = out_b[threadIdx.x];
        const float* wr = out_w + (size_t)threadIdx.x * HID;
#pragma unroll 8
        for (int k = 0; k < HID; k++) acc += wr[k] * h[k];
        out[(size_t)b * LBL + threadIdx.x] = acc;
    }
}

// ---------------------------------------------------------------------------
// Launch
// ---------------------------------------------------------------------------
extern "C" void kernel_launch(void* const* d_in, const int* in_sizes, int n_in,
                              void* d_out, int out_size) {
    const float* inputs    = (const float*)d_in[0];
    const float* proj_w    = (const float*)d_in[4];
    const float* proj_b    = (const float*)d_in[5];
    const float* w_ih0     = (const float*)d_in[6];
    const float* w_hh0     = (const float*)d_in[7];
    const float* b_ih0     = (const float*)d_in[8];
    const float* b_hh0     = (const float*)d_in[9];
    const float* w_ih_rest = (const float*)d_in[10];
    const float* w_hh_rest = (const float*)d_in[11];
    const float* b_ih_rest = (const float*)d_in[12];
    const float* b_hh_rest = (const float*)d_in[13];
    const float* out_w     = (const float*)d_in[14];
    const float* out_b     = (const float*)d_in[15];
    float* out = (float*)d_out;

    combine_kernel<<<dim3(DIN / 32, G4 / 32), dim3(32, 32)>>>(proj_w, w_ih0);
    bias0_kernel<<<1, G4>>>(proj_b, w_ih0, b_ih0, b_hh0);

    xpre0_kernel<<<dim3((L_OUT + 127) / 128, G4 / 64, BATCH), 256>>>(inputs);

    scan_kernel<<<BATCH * 2, 256>>>(w_hh0);

    for (int l = 0; l < 3; l++) {
        gemm_ih_kernel<<<dim3((L_OUT + 63) / 64, G4 / 64, BATCH), 256>>>(
            w_ih_rest + (size_t)l * G4 * HID,
            b_ih_rest + (size_t)l * G4,
            b_hh_rest + (size_t)l * G4);
        scan_kernel<<<BATCH * 2, 256>>>(w_hh_rest + (size_t)l * G4 * HID);
    }

    out_kernel<<<BATCH, 128>>>(out_w, out_b, out);
}